// round 1
// baseline (speedup 1.0000x reference)
#include <cuda_runtime.h>

#define EDIM  1024
#define HEADS 16
#define HD    64
#define WIN   256
#define BATCH 2
#define SEQ   2048
#define MROWS (BATCH*SEQ)   // 4096

// scratch (allocation-free rule: device globals)
static __device__ float g_q[BATCH*SEQ*EDIM];
static __device__ float g_k[BATCH*SEQ*EDIM];
static __device__ float g_v[BATCH*SEQ*EDIM];
static __device__ float g_y[BATCH*SEQ*EDIM];

// ---------------- packed f32x2 helpers (Blackwell FFMA2 pipe) ----------------
__device__ __forceinline__ unsigned long long pack2(float lo, float hi) {
    unsigned long long r;
    asm("mov.b64 %0, {%1,%2};" : "=l"(r)
        : "r"(__float_as_uint(lo)), "r"(__float_as_uint(hi)));
    return r;
}
__device__ __forceinline__ void unpack2(unsigned long long v, float& lo, float& hi) {
    unsigned int a, b;
    asm("mov.b64 {%0,%1}, %2;" : "=r"(a), "=r"(b) : "l"(v));
    lo = __uint_as_float(a); hi = __uint_as_float(b);
}
__device__ __forceinline__ unsigned long long ffma2(unsigned long long a,
                                                    unsigned long long b,
                                                    unsigned long long c) {
    unsigned long long d;
    asm("fma.rn.f32x2 %0, %1, %2, %3;" : "=l"(d) : "l"(a), "l"(b), "l"(c));
    return d;
}
__device__ __forceinline__ unsigned long long fmul2(unsigned long long a,
                                                    unsigned long long b) {
    unsigned long long d;
    asm("mul.rn.f32x2 %0, %1, %2;" : "=l"(d) : "l"(a), "l"(b));
    return d;
}

// ---------------- GEMM: C[4096x1024] = (A @ W^T + bias) * scale ----------------
// A row-major (M,K), W row-major (N,K) -> both K-contiguous (NT case).
// BM=BN=128, BK=16, 256 threads, 8x8 microtile via 8x4 packed f32x2 accumulators.
__global__ __launch_bounds__(256)
void gemm_bias(const float* __restrict__ A, const float* __restrict__ W,
               const float* __restrict__ bias, float* __restrict__ C, float scale)
{
    __shared__ __align__(16) float As[16][128];
    __shared__ __align__(16) float Ws[16][128];

    const int tid = threadIdx.x;
    const int tx  = tid & 15;        // column group (8 cols)
    const int ty  = tid >> 4;        // row group (8 rows)
    const int bm  = blockIdx.y * 128;
    const int bn  = blockIdx.x * 128;

    // loader: each thread owns 1 row-half: row = tid>>1, k offset = (tid&1)*8
    const int lrow = tid >> 1;
    const int lk   = (tid & 1) * 8;

    const float* Aptr = A + (size_t)(bm + lrow) * 1024 + lk;
    const float* Wptr = W + (size_t)(bn + lrow) * 1024 + lk;

    float4 ra0 = *(const float4*)(Aptr + 0);
    float4 ra1 = *(const float4*)(Aptr + 4);
    float4 rw0 = *(const float4*)(Wptr + 0);
    float4 rw1 = *(const float4*)(Wptr + 4);

    unsigned long long acc[8][4];
#pragma unroll
    for (int i = 0; i < 8; i++)
#pragma unroll
        for (int j = 0; j < 4; j++) acc[i][j] = 0ull;

    const int NK = 1024 / 16;
    for (int kk = 0; kk < NK; kk++) {
        As[lk+0][lrow] = ra0.x; As[lk+1][lrow] = ra0.y;
        As[lk+2][lrow] = ra0.z; As[lk+3][lrow] = ra0.w;
        As[lk+4][lrow] = ra1.x; As[lk+5][lrow] = ra1.y;
        As[lk+6][lrow] = ra1.z; As[lk+7][lrow] = ra1.w;
        Ws[lk+0][lrow] = rw0.x; Ws[lk+1][lrow] = rw0.y;
        Ws[lk+2][lrow] = rw0.z; Ws[lk+3][lrow] = rw0.w;
        Ws[lk+4][lrow] = rw1.x; Ws[lk+5][lrow] = rw1.y;
        Ws[lk+6][lrow] = rw1.z; Ws[lk+7][lrow] = rw1.w;
        __syncthreads();

        if (kk + 1 < NK) {          // register prefetch of next tile
            Aptr += 16; Wptr += 16;
            ra0 = *(const float4*)(Aptr + 0);
            ra1 = *(const float4*)(Aptr + 4);
            rw0 = *(const float4*)(Wptr + 0);
            rw1 = *(const float4*)(Wptr + 4);
        }

#pragma unroll
        for (int k = 0; k < 16; k++) {
            float4 a0 = *(const float4*)&As[k][ty*8];
            float4 a1 = *(const float4*)&As[k][ty*8+4];
            ulonglong2 b01 = *(const ulonglong2*)&Ws[k][tx*8];
            ulonglong2 b23 = *(const ulonglong2*)&Ws[k][tx*8+4];
            unsigned long long bb[4] = {b01.x, b01.y, b23.x, b23.y};
            float av[8] = {a0.x,a0.y,a0.z,a0.w,a1.x,a1.y,a1.z,a1.w};
#pragma unroll
            for (int i = 0; i < 8; i++) {
                unsigned long long ad = pack2(av[i], av[i]);
#pragma unroll
                for (int j = 0; j < 4; j++) acc[i][j] = ffma2(ad, bb[j], acc[i][j]);
            }
        }
        __syncthreads();
    }

    float4 bv0 = *(const float4*)(bias + bn + tx*8);
    float4 bv1 = *(const float4*)(bias + bn + tx*8 + 4);
    float bvv[8] = {bv0.x,bv0.y,bv0.z,bv0.w,bv1.x,bv1.y,bv1.z,bv1.w};

#pragma unroll
    for (int i = 0; i < 8; i++) {
        float out[8];
#pragma unroll
        for (int j = 0; j < 4; j++) unpack2(acc[i][j], out[2*j], out[2*j+1]);
#pragma unroll
        for (int c = 0; c < 8; c++) out[c] = (out[c] + bvv[c]) * scale;
        float* crow = C + (size_t)(bm + ty*8 + i) * 1024 + bn + tx*8;
        *(float4*)(crow + 0) = make_float4(out[0],out[1],out[2],out[3]);
        *(float4*)(crow + 4) = make_float4(out[4],out[5],out[6],out[7]);
    }
}

// ---------------- sliding-window flash attention ----------------
// block = (b, h, 64-query tile); 256 threads = 16x16 grid, each thread 4 rows x 4 cols.
__global__ __launch_bounds__(256)
void swattn(const float* __restrict__ Q, const float* __restrict__ K,
            const float* __restrict__ V, float* __restrict__ Y)
{
    extern __shared__ __align__(16) float sm[];
    float* Qt = sm;            // [64][64] transposed: Qt[d*64 + r]
    float* Kt = sm + 4096;     // [64][64] transposed: Kt[d*64 + c]
    float* Vs = sm + 8192;     // [64][64] direct:     Vs[j*64 + c]
    float* Ps = sm + 12288;    // [64][64] probs:      Ps[r*64 + j]

    const int tid = threadIdx.x;
    const int tx  = tid & 15;
    const int ty  = tid >> 4;
    const int qt  = blockIdx.x;      // query tile, 0..31
    const int h   = blockIdx.y;
    const int b   = blockIdx.z;
    const int q0  = qt * 64;

    const size_t baseoff = (size_t)b * SEQ * EDIM + (size_t)h * HD;

    // load Q tile transposed (q already scaled by D^-0.5 in projection)
    {
        const int row = tid >> 2;
        const float* qrow = Q + baseoff + (size_t)(q0 + row) * EDIM;
#pragma unroll
        for (int l2 = 0; l2 < 4; l2++) {
            int f = (tid & 3) + l2 * 4;
            float4 v4 = *(const float4*)(qrow + f*4);
            Qt[(f*4+0)*64 + row] = v4.x; Qt[(f*4+1)*64 + row] = v4.y;
            Qt[(f*4+2)*64 + row] = v4.z; Qt[(f*4+3)*64 + row] = v4.w;
        }
    }

    unsigned long long acc[4][2];
#pragma unroll
    for (int r = 0; r < 4; r++) { acc[r][0] = 0ull; acc[r][1] = 0ull; }
    float m[4] = {-1e30f,-1e30f,-1e30f,-1e30f};
    float l[4] = {0.f,0.f,0.f,0.f};

    const int kb0 = (q0 >= WIN) ? ((q0 - WIN) >> 6) : 0;

    for (int kb = kb0; kb <= qt; kb++) {
        __syncthreads();   // protect Qt (first iter) / Kt,Vs,Ps reuse
        {
            const int row = tid >> 2;
            const float* krow = K + baseoff + (size_t)(kb*64 + row) * EDIM;
            const float* vrow = V + baseoff + (size_t)(kb*64 + row) * EDIM;
#pragma unroll
            for (int l2 = 0; l2 < 4; l2++) {
                int f = (tid & 3) + l2 * 4;
                float4 kv = *(const float4*)(krow + f*4);
                Kt[(f*4+0)*64 + row] = kv.x; Kt[(f*4+1)*64 + row] = kv.y;
                Kt[(f*4+2)*64 + row] = kv.z; Kt[(f*4+3)*64 + row] = kv.w;
                float4 vv = *(const float4*)(vrow + f*4);
                *(float4*)&Vs[row*64 + f*4] = vv;
            }
        }
        __syncthreads();

        // S = Q K^T (64x64), 4x4 per thread, packed f32x2
        unsigned long long s2[4][2];
#pragma unroll
        for (int r = 0; r < 4; r++) { s2[r][0] = 0ull; s2[r][1] = 0ull; }
#pragma unroll 8
        for (int d = 0; d < 64; d++) {
            float4 qv = *(const float4*)&Qt[d*64 + ty*4];
            ulonglong2 kp = *(const ulonglong2*)&Kt[d*64 + tx*4];
            float qa[4] = {qv.x, qv.y, qv.z, qv.w};
#pragma unroll
            for (int r = 0; r < 4; r++) {
                unsigned long long qd = pack2(qa[r], qa[r]);
                s2[r][0] = ffma2(qd, kp.x, s2[r][0]);
                s2[r][1] = ffma2(qd, kp.y, s2[r][1]);
            }
        }

        float s[4][4];
#pragma unroll
        for (int r = 0; r < 4; r++) {
            unpack2(s2[r][0], s[r][0], s[r][1]);
            unpack2(s2[r][1], s[r][2], s[r][3]);
        }

        // mask only needed on diagonal block (causal) and lowest block (window)
        if (kb == qt || kb == qt - 4) {
#pragma unroll
            for (int r = 0; r < 4; r++) {
                int i = q0 + ty*4 + r;
#pragma unroll
                for (int c = 0; c < 4; c++) {
                    int j = kb*64 + tx*4 + c;
                    if (j > i || i - j > WIN) s[r][c] = -1e30f;
                }
            }
        }

        // online softmax (row groups of 16 threads)
#pragma unroll
        for (int r = 0; r < 4; r++) {
            float mx = fmaxf(fmaxf(s[r][0], s[r][1]), fmaxf(s[r][2], s[r][3]));
            mx = fmaxf(mx, __shfl_xor_sync(0xffffffffu, mx, 1, 16));
            mx = fmaxf(mx, __shfl_xor_sync(0xffffffffu, mx, 2, 16));
            mx = fmaxf(mx, __shfl_xor_sync(0xffffffffu, mx, 4, 16));
            mx = fmaxf(mx, __shfl_xor_sync(0xffffffffu, mx, 8, 16));
            float mn = fmaxf(m[r], mx);
            float alpha = __expf(m[r] - mn);
            m[r] = mn;
            float rs = 0.f;
#pragma unroll
            for (int c = 0; c < 4; c++) { s[r][c] = __expf(s[r][c] - mn); rs += s[r][c]; }
            rs += __shfl_xor_sync(0xffffffffu, rs, 1, 16);
            rs += __shfl_xor_sync(0xffffffffu, rs, 2, 16);
            rs += __shfl_xor_sync(0xffffffffu, rs, 4, 16);
            rs += __shfl_xor_sync(0xffffffffu, rs, 8, 16);
            l[r] = l[r] * alpha + rs;
            unsigned long long ap = pack2(alpha, alpha);
            acc[r][0] = fmul2(acc[r][0], ap);
            acc[r][1] = fmul2(acc[r][1], ap);
            *(float4*)&Ps[(ty*4+r)*64 + tx*4] = make_float4(s[r][0],s[r][1],s[r][2],s[r][3]);
        }
        __syncthreads();

        // O += P @ V
#pragma unroll 4
        for (int j = 0; j < 64; j++) {
            ulonglong2 vp = *(const ulonglong2*)&Vs[j*64 + tx*4];
#pragma unroll
            for (int r = 0; r < 4; r++) {
                float p = Ps[(ty*4+r)*64 + j];
                unsigned long long pd = pack2(p, p);
                acc[r][0] = ffma2(pd, vp.x, acc[r][0]);
                acc[r][1] = ffma2(pd, vp.y, acc[r][1]);
            }
        }
    }

    // epilogue: Y[b, q0+row, h*64 + col] = acc / l
#pragma unroll
    for (int r = 0; r < 4; r++) {
        float inv = 1.0f / l[r];
        float o[4];
        unpack2(acc[r][0], o[0], o[1]);
        unpack2(acc[r][1], o[2], o[3]);
        float* yrow = Y + baseoff + (size_t)(q0 + ty*4 + r) * EDIM + tx*4;
        *(float4*)yrow = make_float4(o[0]*inv, o[1]*inv, o[2]*inv, o[3]*inv);
    }
}

// ---------------- launch ----------------
extern "C" void kernel_launch(void* const* d_in, const int* in_sizes, int n_in,
                              void* d_out, int out_size)
{
    const float* x  = (const float*)d_in[0];
    const float* Wq = (const float*)d_in[1];
    const float* Wk = (const float*)d_in[2];
    const float* Wv = (const float*)d_in[3];
    const float* Wo = (const float*)d_in[4];
    const float* bq = (const float*)d_in[5];
    const float* bk = (const float*)d_in[6];
    const float* bv = (const float*)d_in[7];
    const float* bo = (const float*)d_in[8];

    float *q, *k, *v, *y;
    cudaGetSymbolAddress((void**)&q, g_q);
    cudaGetSymbolAddress((void**)&k, g_k);
    cudaGetSymbolAddress((void**)&v, g_v);
    cudaGetSymbolAddress((void**)&y, g_y);

    dim3 gblk(1024/128, MROWS/128);   // (8, 32)
    gemm_bias<<<gblk, 256>>>(x, Wq, bq, q, 0.125f);  // D^-0.5 = 1/8
    gemm_bias<<<gblk, 256>>>(x, Wk, bk, k, 1.0f);
    gemm_bias<<<gblk, 256>>>(x, Wv, bv, v, 1.0f);

    cudaFuncSetAttribute(swattn, cudaFuncAttributeMaxDynamicSharedMemorySize, 65536);
    swattn<<<dim3(SEQ/64, HEADS, BATCH), 256, 65536>>>(q, k, v, y);

    gemm_bias<<<gblk, 256>>>(y, Wo, bo, (float*)d_out, 1.0f);
}

// round 3
// speedup vs baseline: 1.5056x; 1.5056x over previous
#include <cuda_runtime.h>
#include <cuda_bf16.h>
#include <cstdint>

#define EDIM  1024
#define HEADS 16
#define HD    64
#define WIN   256
#define BATCH 2
#define SEQ   2048
#define MROWS (BATCH*SEQ)   // 4096
#define KTOT  3072          // concatenated split-K: [hi|hi|lo] x [hi|lo|hi]

// ---------------- scratch (allocation-free rule: device globals) ----------------
static __device__ float g_q[MROWS*EDIM];
static __device__ float g_k[MROWS*EDIM];
static __device__ float g_v[MROWS*EDIM];
static __device__ float g_y[MROWS*EDIM];
static __device__ __nv_bfloat16 g_xs[MROWS*KTOT];      // split x  [Ah|Ah|Al]
static __device__ __nv_bfloat16 g_ys[MROWS*KTOT];      // split y
static __device__ __nv_bfloat16 g_ws[4][EDIM*KTOT];    // split W  [Wh|Wl|Wh]

// ---------------- small PTX helpers (ALL family-common, no 'a'-target ops) -----
__device__ __forceinline__ uint32_t smem_to_u32(const void* p) {
    uint32_t a;
    asm("{ .reg .u64 t; cvta.to.shared.u64 t, %1; cvt.u32.u64 %0, t; }"
        : "=r"(a) : "l"(p));
    return a;
}
__device__ __forceinline__ void cp_async16(uint32_t dst, const void* src) {
    asm volatile("cp.async.cg.shared.global [%0], [%1], 16;" :: "r"(dst), "l"(src));
}
#define CP_COMMIT() asm volatile("cp.async.commit_group;" ::: "memory")
#define CP_WAIT1()  asm volatile("cp.async.wait_group 1;" ::: "memory")
#define CP_WAIT0()  asm volatile("cp.async.wait_group 0;" ::: "memory")

__device__ __forceinline__ void ldsm4(uint32_t& r0, uint32_t& r1, uint32_t& r2,
                                      uint32_t& r3, uint32_t addr) {
    asm volatile("ldmatrix.sync.aligned.m8n8.x4.shared.b16 {%0,%1,%2,%3}, [%4];"
                 : "=r"(r0), "=r"(r1), "=r"(r2), "=r"(r3) : "r"(addr));
}
__device__ __forceinline__ void mma16816(float* c, uint32_t a0, uint32_t a1,
                                         uint32_t a2, uint32_t a3,
                                         uint32_t b0, uint32_t b1) {
    asm volatile(
        "mma.sync.aligned.m16n8k16.row.col.f32.bf16.bf16.f32 "
        "{%0,%1,%2,%3}, {%4,%5,%6,%7}, {%8,%9}, {%0,%1,%2,%3};"
        : "+f"(c[0]), "+f"(c[1]), "+f"(c[2]), "+f"(c[3])
        : "r"(a0), "r"(a1), "r"(a2), "r"(a3), "r"(b0), "r"(b1));
}

// ---------------- fp32 -> split-bf16 (writes 3 K-slabs) ----------------
// hi at col, hi again at col+hi2, lo at col+lo.
__global__ __launch_bounds__(256)
void split3(const float* __restrict__ in, __nv_bfloat16* __restrict__ out,
            int hi2, int lo, int n4)
{
    int i = blockIdx.x * 256 + threadIdx.x;
    if (i >= n4) return;
    int r = i >> 8;               // 256 float4 per 1024-row
    int c = (i & 255) * 4;
    float4 v = ((const float4*)in)[i];
    float vv[4] = {v.x, v.y, v.z, v.w};
    __nv_bfloat16 h[4], l[4];
#pragma unroll
    for (int j = 0; j < 4; j++) {
        h[j] = __float2bfloat16_rn(vv[j]);
        l[j] = __float2bfloat16_rn(vv[j] - __bfloat162float(h[j]));
    }
    __nv_bfloat16* row = out + (size_t)r * KTOT;
    uint2 hp = *(uint2*)h, lp = *(uint2*)l;
    *(uint2*)(row + c)        = hp;
    *(uint2*)(row + hi2 + c)  = hp;
    *(uint2*)(row + lo + c)   = lp;
}

// ---------------- bf16 warp-MMA GEMM ----------------
// C[4096x1024] = scale * (A'[4096x3072] @ B'[1024x3072]^T + bias)
// CTA tile 128x128, 8 warps each 32x64, BK=32, double-buffered cp.async.
#define BK  32
#define LDS 40    // padded smem row stride (bf16)

__global__ __launch_bounds__(256)
void gemm_mma(const __nv_bfloat16* __restrict__ A, const __nv_bfloat16* __restrict__ B,
              const float* __restrict__ bias, float* __restrict__ C, float scale)
{
    __shared__ __align__(16) __nv_bfloat16 As[2][128 * LDS];
    __shared__ __align__(16) __nv_bfloat16 Bs[2][128 * LDS];

    const int tid  = threadIdx.x;
    const int wid  = tid >> 5;
    const int lane = tid & 31;
    const int bm   = blockIdx.y * 128;
    const int bn   = blockIdx.x * 128;
    const int wm   = (wid & 3) * 32;    // warp m offset in tile
    const int wn   = (wid >> 2) * 64;   // warp n offset in tile

    const __nv_bfloat16* Abase = A + (size_t)bm * KTOT;
    const __nv_bfloat16* Bbase = B + (size_t)bn * KTOT;

    // loader mapping: idx = tid + i*256 -> row = idx>>2, seg = idx&3 (16B segs)
    const int lrow0 = tid >> 2, lseg0 = tid & 3;
    const int lrow1 = (tid + 256) >> 2, lseg1 = tid & 3;

    float acc[2][8][4];
#pragma unroll
    for (int mt = 0; mt < 2; mt++)
#pragma unroll
        for (int nt = 0; nt < 8; nt++)
#pragma unroll
            for (int j = 0; j < 4; j++) acc[mt][nt][j] = 0.f;

    // ldmatrix smem addresses (per lane)
    const int a_row = lane & 15, a_ch = (lane >> 4);             // A: rows 0-15, col half
    const int b_nin = (lane & 7) + ((lane >= 16) ? 8 : 0);       // B: n within 16
    const int b_ch  = (lane >> 3) & 1;                            // B: col half

#define LOAD_CHUNK(kc, buf) do { \
    const __nv_bfloat16* a0 = Abase + (size_t)(kc) * BK; \
    const __nv_bfloat16* b0 = Bbase + (size_t)(kc) * BK; \
    cp_async16(smem_to_u32(&As[buf][lrow0 * LDS + lseg0 * 8]), a0 + (size_t)lrow0 * KTOT + lseg0 * 8); \
    cp_async16(smem_to_u32(&As[buf][lrow1 * LDS + lseg1 * 8]), a0 + (size_t)lrow1 * KTOT + lseg1 * 8); \
    cp_async16(smem_to_u32(&Bs[buf][lrow0 * LDS + lseg0 * 8]), b0 + (size_t)lrow0 * KTOT + lseg0 * 8); \
    cp_async16(smem_to_u32(&Bs[buf][lrow1 * LDS + lseg1 * 8]), b0 + (size_t)lrow1 * KTOT + lseg1 * 8); \
} while (0)

    LOAD_CHUNK(0, 0);
    CP_COMMIT();

    const int NCHUNK = KTOT / BK;   // 96
    for (int c = 0; c < NCHUNK; c++) {
        const int buf = c & 1;
        if (c + 1 < NCHUNK) {
            LOAD_CHUNK(c + 1, buf ^ 1);
            CP_COMMIT();
            CP_WAIT1();
        } else {
            CP_WAIT0();
        }
        __syncthreads();

#pragma unroll
        for (int ks = 0; ks < 2; ks++) {
            const int k0 = ks * 16;
            uint32_t a[2][4];
#pragma unroll
            for (int mt = 0; mt < 2; mt++) {
                uint32_t addr = smem_to_u32(
                    &As[buf][(wm + mt * 16 + a_row) * LDS + k0 + a_ch * 8]);
                ldsm4(a[mt][0], a[mt][1], a[mt][2], a[mt][3], addr);
            }
            uint32_t b[8][2];
#pragma unroll
            for (int p = 0; p < 4; p++) {
                uint32_t r0, r1, r2, r3;
                uint32_t addr = smem_to_u32(
                    &Bs[buf][(wn + p * 16 + b_nin) * LDS + k0 + b_ch * 8]);
                ldsm4(r0, r1, r2, r3, addr);
                b[2 * p][0] = r0; b[2 * p][1] = r1;
                b[2 * p + 1][0] = r2; b[2 * p + 1][1] = r3;
            }
#pragma unroll
            for (int mt = 0; mt < 2; mt++)
#pragma unroll
                for (int nt = 0; nt < 8; nt++)
                    mma16816(acc[mt][nt], a[mt][0], a[mt][1], a[mt][2], a[mt][3],
                             b[nt][0], b[nt][1]);
        }
        __syncthreads();
    }

    // epilogue
#pragma unroll
    for (int nt = 0; nt < 8; nt++) {
        const int col = bn + wn + nt * 8 + (lane & 3) * 2;
        const float b0 = bias[col], b1 = bias[col + 1];
#pragma unroll
        for (int mt = 0; mt < 2; mt++) {
            const int r0 = bm + wm + mt * 16 + (lane >> 2);
            float2 v0 = make_float2((acc[mt][nt][0] + b0) * scale,
                                    (acc[mt][nt][1] + b1) * scale);
            float2 v1 = make_float2((acc[mt][nt][2] + b0) * scale,
                                    (acc[mt][nt][3] + b1) * scale);
            *(float2*)&C[(size_t)r0 * EDIM + col] = v0;
            *(float2*)&C[(size_t)(r0 + 8) * EDIM + col] = v1;
        }
    }
#undef LOAD_CHUNK
}

// ---------------- packed f32x2 helpers (attention) ----------------
__device__ __forceinline__ unsigned long long pack2(float lo, float hi) {
    unsigned long long r;
    asm("mov.b64 %0, {%1,%2};" : "=l"(r)
        : "r"(__float_as_uint(lo)), "r"(__float_as_uint(hi)));
    return r;
}
__device__ __forceinline__ void unpack2(unsigned long long v, float& lo, float& hi) {
    unsigned int a, b;
    asm("mov.b64 {%0,%1}, %2;" : "=r"(a), "=r"(b) : "l"(v));
    lo = __uint_as_float(a); hi = __uint_as_float(b);
}
__device__ __forceinline__ unsigned long long ffma2(unsigned long long a,
                                                    unsigned long long b,
                                                    unsigned long long c) {
    unsigned long long d;
    asm("fma.rn.f32x2 %0, %1, %2, %3;" : "=l"(d) : "l"(a), "l"(b), "l"(c));
    return d;
}
__device__ __forceinline__ unsigned long long fmul2(unsigned long long a,
                                                    unsigned long long b) {
    unsigned long long d;
    asm("mul.rn.f32x2 %0, %1, %2;" : "=l"(d) : "l"(a), "l"(b));
    return d;
}

// ---------------- sliding-window flash attention (fp32, f32x2 pipe) ----------------
__global__ __launch_bounds__(256)
void swattn(const float* __restrict__ Q, const float* __restrict__ K,
            const float* __restrict__ V, float* __restrict__ Y)
{
    extern __shared__ __align__(16) float sm[];
    float* Qt = sm;            // [64][64] transposed
    float* Kt = sm + 4096;     // [64][64] transposed
    float* Vs = sm + 8192;     // [64][64] direct
    float* Ps = sm + 12288;    // [64][64] probs

    const int tid = threadIdx.x;
    const int tx  = tid & 15;
    const int ty  = tid >> 4;
    const int qt  = blockIdx.x;
    const int h   = blockIdx.y;
    const int b   = blockIdx.z;
    const int q0  = qt * 64;

    const size_t baseoff = (size_t)b * SEQ * EDIM + (size_t)h * HD;

    {
        const int row = tid >> 2;
        const float* qrow = Q + baseoff + (size_t)(q0 + row) * EDIM;
#pragma unroll
        for (int l2 = 0; l2 < 4; l2++) {
            int f = (tid & 3) + l2 * 4;
            float4 v4 = *(const float4*)(qrow + f*4);
            Qt[(f*4+0)*64 + row] = v4.x; Qt[(f*4+1)*64 + row] = v4.y;
            Qt[(f*4+2)*64 + row] = v4.z; Qt[(f*4+3)*64 + row] = v4.w;
        }
    }

    unsigned long long acc[4][2];
#pragma unroll
    for (int r = 0; r < 4; r++) { acc[r][0] = 0ull; acc[r][1] = 0ull; }
    float m[4] = {-1e30f,-1e30f,-1e30f,-1e30f};
    float l[4] = {0.f,0.f,0.f,0.f};

    const int kb0 = (q0 >= WIN) ? ((q0 - WIN) >> 6) : 0;

    for (int kb = kb0; kb <= qt; kb++) {
        __syncthreads();
        {
            const int row = tid >> 2;
            const float* krow = K + baseoff + (size_t)(kb*64 + row) * EDIM;
            const float* vrow = V + baseoff + (size_t)(kb*64 + row) * EDIM;
#pragma unroll
            for (int l2 = 0; l2 < 4; l2++) {
                int f = (tid & 3) + l2 * 4;
                float4 kv = *(const float4*)(krow + f*4);
                Kt[(f*4+0)*64 + row] = kv.x; Kt[(f*4+1)*64 + row] = kv.y;
                Kt[(f*4+2)*64 + row] = kv.z; Kt[(f*4+3)*64 + row] = kv.w;
                float4 vv = *(const float4*)(vrow + f*4);
                *(float4*)&Vs[row*64 + f*4] = vv;
            }
        }
        __syncthreads();

        unsigned long long s2[4][2];
#pragma unroll
        for (int r = 0; r < 4; r++) { s2[r][0] = 0ull; s2[r][1] = 0ull; }
#pragma unroll 8
        for (int d = 0; d < 64; d++) {
            float4 qv = *(const float4*)&Qt[d*64 + ty*4];
            ulonglong2 kp = *(const ulonglong2*)&Kt[d*64 + tx*4];
            float qa[4] = {qv.x, qv.y, qv.z, qv.w};
#pragma unroll
            for (int r = 0; r < 4; r++) {
                unsigned long long qd = pack2(qa[r], qa[r]);
                s2[r][0] = ffma2(qd, kp.x, s2[r][0]);
                s2[r][1] = ffma2(qd, kp.y, s2[r][1]);
            }
        }

        float s[4][4];
#pragma unroll
        for (int r = 0; r < 4; r++) {
            unpack2(s2[r][0], s[r][0], s[r][1]);
            unpack2(s2[r][1], s[r][2], s[r][3]);
        }

        if (kb == qt || kb == qt - 4) {
#pragma unroll
            for (int r = 0; r < 4; r++) {
                int i = q0 + ty*4 + r;
#pragma unroll
                for (int c = 0; c < 4; c++) {
                    int j = kb*64 + tx*4 + c;
                    if (j > i || i - j > WIN) s[r][c] = -1e30f;
                }
            }
        }

#pragma unroll
        for (int r = 0; r < 4; r++) {
            float mx = fmaxf(fmaxf(s[r][0], s[r][1]), fmaxf(s[r][2], s[r][3]));
            mx = fmaxf(mx, __shfl_xor_sync(0xffffffffu, mx, 1, 16));
            mx = fmaxf(mx, __shfl_xor_sync(0xffffffffu, mx, 2, 16));
            mx = fmaxf(mx, __shfl_xor_sync(0xffffffffu, mx, 4, 16));
            mx = fmaxf(mx, __shfl_xor_sync(0xffffffffu, mx, 8, 16));
            float mn = fmaxf(m[r], mx);
            float alpha = __expf(m[r] - mn);
            m[r] = mn;
            float rs = 0.f;
#pragma unroll
            for (int c = 0; c < 4; c++) { s[r][c] = __expf(s[r][c] - mn); rs += s[r][c]; }
            rs += __shfl_xor_sync(0xffffffffu, rs, 1, 16);
            rs += __shfl_xor_sync(0xffffffffu, rs, 2, 16);
            rs += __shfl_xor_sync(0xffffffffu, rs, 4, 16);
            rs += __shfl_xor_sync(0xffffffffu, rs, 8, 16);
            l[r] = l[r] * alpha + rs;
            unsigned long long ap = pack2(alpha, alpha);
            acc[r][0] = fmul2(acc[r][0], ap);
            acc[r][1] = fmul2(acc[r][1], ap);
            *(float4*)&Ps[(ty*4+r)*64 + tx*4] = make_float4(s[r][0],s[r][1],s[r][2],s[r][3]);
        }
        __syncthreads();

#pragma unroll 4
        for (int j = 0; j < 64; j++) {
            ulonglong2 vp = *(const ulonglong2*)&Vs[j*64 + tx*4];
#pragma unroll
            for (int r = 0; r < 4; r++) {
                float p = Ps[(ty*4+r)*64 + j];
                unsigned long long pd = pack2(p, p);
                acc[r][0] = ffma2(pd, vp.x, acc[r][0]);
                acc[r][1] = ffma2(pd, vp.y, acc[r][1]);
            }
        }
    }

#pragma unroll
    for (int r = 0; r < 4; r++) {
        float inv = 1.0f / l[r];
        float o[4];
        unpack2(acc[r][0], o[0], o[1]);
        unpack2(acc[r][1], o[2], o[3]);
        float* yrow = Y + baseoff + (size_t)(q0 + ty*4 + r) * EDIM + tx*4;
        *(float4*)yrow = make_float4(o[0]*inv, o[1]*inv, o[2]*inv, o[3]*inv);
    }
}

// ---------------- launch ----------------
extern "C" void kernel_launch(void* const* d_in, const int* in_sizes, int n_in,
                              void* d_out, int out_size)
{
    const float* x  = (const float*)d_in[0];
    const float* Wq = (const float*)d_in[1];
    const float* Wk = (const float*)d_in[2];
    const float* Wv = (const float*)d_in[3];
    const float* Wo = (const float*)d_in[4];
    const float* bq = (const float*)d_in[5];
    const float* bk = (const float*)d_in[6];
    const float* bv = (const float*)d_in[7];
    const float* bo = (const float*)d_in[8];

    float *q, *k, *v, *y;
    __nv_bfloat16 *xs, *ys, *ws;
    cudaGetSymbolAddress((void**)&q,  g_q);
    cudaGetSymbolAddress((void**)&k,  g_k);
    cudaGetSymbolAddress((void**)&v,  g_v);
    cudaGetSymbolAddress((void**)&y,  g_y);
    cudaGetSymbolAddress((void**)&xs, g_xs);
    cudaGetSymbolAddress((void**)&ys, g_ys);
    cudaGetSymbolAddress((void**)&ws, g_ws);

    static bool attr_done = false;
    if (!attr_done) {
        cudaFuncSetAttribute(swattn, cudaFuncAttributeMaxDynamicSharedMemorySize, 65536);
        attr_done = true;
    }

    const int NX4 = MROWS * EDIM / 4;
    const int NW4 = EDIM * EDIM / 4;

    // activations: [Ah|Ah|Al]  (hi dup at +1024, lo at +2048)
    split3<<<(NX4 + 255) / 256, 256>>>(x, xs, 1024, 2048, NX4);
    // weights: [Wh|Wl|Wh]  (hi dup at +2048, lo at +1024)
    split3<<<(NW4 + 255) / 256, 256>>>(Wq, ws + 0*(size_t)EDIM*KTOT, 2048, 1024, NW4);
    split3<<<(NW4 + 255) / 256, 256>>>(Wk, ws + 1*(size_t)EDIM*KTOT, 2048, 1024, NW4);
    split3<<<(NW4 + 255) / 256, 256>>>(Wv, ws + 2*(size_t)EDIM*KTOT, 2048, 1024, NW4);
    split3<<<(NW4 + 255) / 256, 256>>>(Wo, ws + 3*(size_t)EDIM*KTOT, 2048, 1024, NW4);

    dim3 gg(EDIM / 128, MROWS / 128);   // (8, 32)
    gemm_mma<<<gg, 256>>>(xs, ws + 0*(size_t)EDIM*KTOT, bq, q, 0.125f);
    gemm_mma<<<gg, 256>>>(xs, ws + 1*(size_t)EDIM*KTOT, bk, k, 1.0f);
    gemm_mma<<<gg, 256>>>(xs, ws + 2*(size_t)EDIM*KTOT, bv, v, 1.0f);

    swattn<<<dim3(SEQ/64, HEADS, BATCH), 256, 65536>>>(q, k, v, y);

    split3<<<(NX4 + 255) / 256, 256>>>(y, ys, 1024, 2048, NX4);
    gemm_mma<<<gg, 256>>>(ys, ws + 3*(size_t)EDIM*KTOT, bo, (float*)d_out, 1.0f);
}

// round 4
// speedup vs baseline: 1.9054x; 1.2655x over previous
#include <cuda_runtime.h>
#include <cuda_bf16.h>
#include <cstdint>

#define EDIM  1024
#define HEADS 16
#define HD    64
#define WIN   256
#define BATCH 2
#define SEQ   2048
#define MROWS (BATCH*SEQ)   // 4096

// ---------------- scratch (allocation-free rule: device globals) ----------------
static __device__ float g_q[MROWS*EDIM];
static __device__ float g_k[MROWS*EDIM];
static __device__ float g_v[MROWS*EDIM];
static __device__ float g_y[MROWS*EDIM];
static __device__ __nv_bfloat16 g_xh[MROWS*EDIM];
static __device__ __nv_bfloat16 g_xl[MROWS*EDIM];
static __device__ __nv_bfloat16 g_yh[MROWS*EDIM];
static __device__ __nv_bfloat16 g_yl[MROWS*EDIM];
static __device__ __nv_bfloat16 g_wh[4][EDIM*EDIM];
static __device__ __nv_bfloat16 g_wl[4][EDIM*EDIM];

// ---------------- family-common PTX helpers ----------------
__device__ __forceinline__ uint32_t smem_to_u32(const void* p) {
    uint32_t a;
    asm("{ .reg .u64 t; cvta.to.shared.u64 t, %1; cvt.u32.u64 %0, t; }"
        : "=r"(a) : "l"(p));
    return a;
}
__device__ __forceinline__ void cp_async16(uint32_t dst, const void* src) {
    asm volatile("cp.async.cg.shared.global [%0], [%1], 16;" :: "r"(dst), "l"(src));
}
#define CP_COMMIT() asm volatile("cp.async.commit_group;" ::: "memory")
#define CP_WAIT1()  asm volatile("cp.async.wait_group 1;" ::: "memory")
#define CP_WAIT0()  asm volatile("cp.async.wait_group 0;" ::: "memory")

__device__ __forceinline__ void ldsm4(uint32_t& r0, uint32_t& r1, uint32_t& r2,
                                      uint32_t& r3, uint32_t addr) {
    asm volatile("ldmatrix.sync.aligned.m8n8.x4.shared.b16 {%0,%1,%2,%3}, [%4];"
                 : "=r"(r0), "=r"(r1), "=r"(r2), "=r"(r3) : "r"(addr));
}
__device__ __forceinline__ void mma16816(float* c, uint32_t a0, uint32_t a1,
                                         uint32_t a2, uint32_t a3,
                                         uint32_t b0, uint32_t b1) {
    asm volatile(
        "mma.sync.aligned.m16n8k16.row.col.f32.bf16.bf16.f32 "
        "{%0,%1,%2,%3}, {%4,%5,%6,%7}, {%8,%9}, {%0,%1,%2,%3};"
        : "+f"(c[0]), "+f"(c[1]), "+f"(c[2]), "+f"(c[3])
        : "r"(a0), "r"(a1), "r"(a2), "r"(a3), "r"(b0), "r"(b1));
}

// ---------------- fp32 -> bf16 hi/lo split ----------------
__global__ __launch_bounds__(256)
void split_bf16(const float* __restrict__ in, __nv_bfloat16* __restrict__ hi,
                __nv_bfloat16* __restrict__ lo, int n4)
{
    int i = blockIdx.x * 256 + threadIdx.x;
    if (i >= n4) return;
    float4 v = ((const float4*)in)[i];
    float vv[4] = {v.x, v.y, v.z, v.w};
    __nv_bfloat16 h[4], l[4];
#pragma unroll
    for (int j = 0; j < 4; j++) {
        h[j] = __float2bfloat16_rn(vv[j]);
        l[j] = __float2bfloat16_rn(vv[j] - __bfloat162float(h[j]));
    }
    ((uint2*)hi)[i] = *(uint2*)h;
    ((uint2*)lo)[i] = *(uint2*)l;
}

// ---------------- bf16 warp-MMA GEMM, 3-segment split-K ----------------
// C = scale * (Ah@Bh^T + Ah@Bl^T + Al@Bh^T + bias)
// 128x128 CTA tile, 8 warps (32x64 each), BK=64, 3-stage cp.async pipeline.
#define BM   128
#define BN   128
#define BKC  64
#define LDSB 72                      // padded bf16 row stride
#define ATILE (BM*LDSB)
#define BTILE (BN*LDSB)
#define GEMM_SMEM (3*(ATILE+BTILE)*2)   // 110,592 B

// grid.z selects {q,k,v} (weights offset z*E*E); for the Wo pass launch z-dim 1.
__global__ __launch_bounds__(256)
void gemm_tc3(const __nv_bfloat16* __restrict__ Ah, const __nv_bfloat16* __restrict__ Al,
              const __nv_bfloat16* __restrict__ Wh, const __nv_bfloat16* __restrict__ Wl,
              const float* __restrict__ b0, const float* __restrict__ b1,
              const float* __restrict__ b2,
              float* __restrict__ O0, float* __restrict__ O1, float* __restrict__ O2,
              float s0)
{
    extern __shared__ __align__(16) __nv_bfloat16 gsm[];
    __nv_bfloat16* As = gsm;                 // 3 stages of BM x BKC
    __nv_bfloat16* Bs = gsm + 3 * ATILE;     // 3 stages of BN x BKC

    const int tid  = threadIdx.x;
    const int wid  = tid >> 5;
    const int lane = tid & 31;
    const int bm   = blockIdx.y * BM;
    const int bn   = blockIdx.x * BN;
    const int z    = blockIdx.z;
    const int wm   = (wid & 3) * 32;
    const int wn   = (wid >> 2) * 64;

    const __nv_bfloat16* Bh = Wh + (size_t)z * EDIM * EDIM + (size_t)bn * EDIM;
    const __nv_bfloat16* Bl = Wl + (size_t)z * EDIM * EDIM + (size_t)bn * EDIM;
    const __nv_bfloat16* Ahb = Ah + (size_t)bm * EDIM;
    const __nv_bfloat16* Alb = Al + (size_t)bm * EDIM;
    const float* bias = (z == 0) ? b0 : (z == 1) ? b1 : b2;
    float*       C    = (z == 0) ? O0 : (z == 1) ? O1 : O2;
    const float scale = (z == 0) ? s0 : 1.0f;

    const __nv_bfloat16* segA[3] = {Ahb, Ahb, Alb};
    const __nv_bfloat16* segB[3] = {Bh,  Bl,  Bh};

    float acc[2][8][4];
#pragma unroll
    for (int mt = 0; mt < 2; mt++)
#pragma unroll
        for (int nt = 0; nt < 8; nt++)
#pragma unroll
            for (int j = 0; j < 4; j++) acc[mt][nt][j] = 0.f;

    const int a_row = lane & 15, a_ch = lane >> 4;
    const int b_nin = (lane & 7) + ((lane >= 16) ? 8 : 0);
    const int b_ch  = (lane >> 3) & 1;

#define LOADC(cc, st) do { \
    const int _seg = (cc) >> 4, _kc = (cc) & 15; \
    const __nv_bfloat16* _a = segA[_seg] + (size_t)_kc * BKC; \
    const __nv_bfloat16* _b = segB[_seg] + (size_t)_kc * BKC; \
    __nv_bfloat16* _as = As + (st) * ATILE; \
    __nv_bfloat16* _bs = Bs + (st) * BTILE; \
    _Pragma("unroll") \
    for (int _i = 0; _i < 4; _i++) { \
        int _idx = tid + _i * 256; int _r = _idx >> 3, _s = _idx & 7; \
        cp_async16(smem_to_u32(&_as[_r * LDSB + _s * 8]), _a + (size_t)_r * EDIM + _s * 8); \
        cp_async16(smem_to_u32(&_bs[_r * LDSB + _s * 8]), _b + (size_t)_r * EDIM + _s * 8); \
    } \
} while (0)

    const int NCH = 48;                 // 3 segments x 16 chunks of 64
    LOADC(0, 0); CP_COMMIT();
    LOADC(1, 1); CP_COMMIT();

    for (int c = 0; c < NCH; c++) {
        CP_WAIT1();
        __syncthreads();
        if (c + 2 < NCH) { LOADC(c + 2, (c + 2) % 3); CP_COMMIT(); }

        const __nv_bfloat16* as = As + (c % 3) * ATILE;
        const __nv_bfloat16* bs = Bs + (c % 3) * BTILE;
#pragma unroll
        for (int ks = 0; ks < 4; ks++) {
            const int k0 = ks * 16;
            uint32_t a[2][4];
#pragma unroll
            for (int mt = 0; mt < 2; mt++) {
                uint32_t addr = smem_to_u32(&as[(wm + mt * 16 + a_row) * LDSB + k0 + a_ch * 8]);
                ldsm4(a[mt][0], a[mt][1], a[mt][2], a[mt][3], addr);
            }
            uint32_t b[8][2];
#pragma unroll
            for (int p = 0; p < 4; p++) {
                uint32_t r0, r1, r2, r3;
                uint32_t addr = smem_to_u32(&bs[(wn + p * 16 + b_nin) * LDSB + k0 + b_ch * 8]);
                ldsm4(r0, r1, r2, r3, addr);
                b[2 * p][0] = r0;     b[2 * p][1] = r1;
                b[2 * p + 1][0] = r2; b[2 * p + 1][1] = r3;
            }
#pragma unroll
            for (int mt = 0; mt < 2; mt++)
#pragma unroll
                for (int nt = 0; nt < 8; nt++)
                    mma16816(acc[mt][nt], a[mt][0], a[mt][1], a[mt][2], a[mt][3],
                             b[nt][0], b[nt][1]);
        }
    }
#undef LOADC

#pragma unroll
    for (int nt = 0; nt < 8; nt++) {
        const int col = bn + wn + nt * 8 + (lane & 3) * 2;
        const float c0 = bias[col], c1 = bias[col + 1];
#pragma unroll
        for (int mt = 0; mt < 2; mt++) {
            const int r0 = bm + wm + mt * 16 + (lane >> 2);
            *(float2*)&C[(size_t)r0 * EDIM + col] =
                make_float2((acc[mt][nt][0] + c0) * scale, (acc[mt][nt][1] + c1) * scale);
            *(float2*)&C[(size_t)(r0 + 8) * EDIM + col] =
                make_float2((acc[mt][nt][2] + c0) * scale, (acc[mt][nt][3] + c1) * scale);
        }
    }
}

// ---------------- packed f32x2 helpers (attention) ----------------
__device__ __forceinline__ unsigned long long pack2(float lo, float hi) {
    unsigned long long r;
    asm("mov.b64 %0, {%1,%2};" : "=l"(r)
        : "r"(__float_as_uint(lo)), "r"(__float_as_uint(hi)));
    return r;
}
__device__ __forceinline__ void unpack2(unsigned long long v, float& lo, float& hi) {
    unsigned int a, b;
    asm("mov.b64 {%0,%1}, %2;" : "=r"(a), "=r"(b) : "l"(v));
    lo = __uint_as_float(a); hi = __uint_as_float(b);
}
__device__ __forceinline__ unsigned long long ffma2(unsigned long long a,
                                                    unsigned long long b,
                                                    unsigned long long c) {
    unsigned long long d;
    asm("fma.rn.f32x2 %0, %1, %2, %3;" : "=l"(d) : "l"(a), "l"(b), "l"(c));
    return d;
}
__device__ __forceinline__ unsigned long long fmul2(unsigned long long a,
                                                    unsigned long long b) {
    unsigned long long d;
    asm("mul.rn.f32x2 %0, %1, %2;" : "=l"(d) : "l"(a), "l"(b));
    return d;
}

// ---------------- sliding-window flash attention (fp32, f32x2 pipe) ----------------
__global__ __launch_bounds__(256)
void swattn(const float* __restrict__ Q, const float* __restrict__ K,
            const float* __restrict__ V, float* __restrict__ Y)
{
    extern __shared__ __align__(16) float sm[];
    float* Qt = sm;            // [64][64] transposed
    float* Kt = sm + 4096;     // [64][64] transposed
    float* Vs = sm + 8192;     // [64][64] direct
    float* Ps = sm + 12288;    // [64][64] probs

    const int tid = threadIdx.x;
    const int tx  = tid & 15;
    const int ty  = tid >> 4;
    const int qt  = blockIdx.x;
    const int h   = blockIdx.y;
    const int b   = blockIdx.z;
    const int q0  = qt * 64;

    const size_t baseoff = (size_t)b * SEQ * EDIM + (size_t)h * HD;

    {
        const int row = tid >> 2;
        const float* qrow = Q + baseoff + (size_t)(q0 + row) * EDIM;
#pragma unroll
        for (int l2 = 0; l2 < 4; l2++) {
            int f = (tid & 3) + l2 * 4;
            float4 v4 = *(const float4*)(qrow + f*4);
            Qt[(f*4+0)*64 + row] = v4.x; Qt[(f*4+1)*64 + row] = v4.y;
            Qt[(f*4+2)*64 + row] = v4.z; Qt[(f*4+3)*64 + row] = v4.w;
        }
    }

    unsigned long long acc[4][2];
#pragma unroll
    for (int r = 0; r < 4; r++) { acc[r][0] = 0ull; acc[r][1] = 0ull; }
    float m[4] = {-1e30f,-1e30f,-1e30f,-1e30f};
    float l[4] = {0.f,0.f,0.f,0.f};

    const int kb0 = (q0 >= WIN) ? ((q0 - WIN) >> 6) : 0;

    for (int kb = kb0; kb <= qt; kb++) {
        __syncthreads();
        {
            const int row = tid >> 2;
            const float* krow = K + baseoff + (size_t)(kb*64 + row) * EDIM;
            const float* vrow = V + baseoff + (size_t)(kb*64 + row) * EDIM;
#pragma unroll
            for (int l2 = 0; l2 < 4; l2++) {
                int f = (tid & 3) + l2 * 4;
                float4 kv = *(const float4*)(krow + f*4);
                Kt[(f*4+0)*64 + row] = kv.x; Kt[(f*4+1)*64 + row] = kv.y;
                Kt[(f*4+2)*64 + row] = kv.z; Kt[(f*4+3)*64 + row] = kv.w;
                float4 vv = *(const float4*)(vrow + f*4);
                *(float4*)&Vs[row*64 + f*4] = vv;
            }
        }
        __syncthreads();

        unsigned long long s2[4][2];
#pragma unroll
        for (int r = 0; r < 4; r++) { s2[r][0] = 0ull; s2[r][1] = 0ull; }
#pragma unroll 8
        for (int d = 0; d < 64; d++) {
            float4 qv = *(const float4*)&Qt[d*64 + ty*4];
            ulonglong2 kp = *(const ulonglong2*)&Kt[d*64 + tx*4];
            float qa[4] = {qv.x, qv.y, qv.z, qv.w};
#pragma unroll
            for (int r = 0; r < 4; r++) {
                unsigned long long qd = pack2(qa[r], qa[r]);
                s2[r][0] = ffma2(qd, kp.x, s2[r][0]);
                s2[r][1] = ffma2(qd, kp.y, s2[r][1]);
            }
        }

        float s[4][4];
#pragma unroll
        for (int r = 0; r < 4; r++) {
            unpack2(s2[r][0], s[r][0], s[r][1]);
            unpack2(s2[r][1], s[r][2], s[r][3]);
        }

        if (kb == qt || kb == qt - 4) {
#pragma unroll
            for (int r = 0; r < 4; r++) {
                int i = q0 + ty*4 + r;
#pragma unroll
                for (int c = 0; c < 4; c++) {
                    int j = kb*64 + tx*4 + c;
                    if (j > i || i - j > WIN) s[r][c] = -1e30f;
                }
            }
        }

#pragma unroll
        for (int r = 0; r < 4; r++) {
            float mx = fmaxf(fmaxf(s[r][0], s[r][1]), fmaxf(s[r][2], s[r][3]));
            mx = fmaxf(mx, __shfl_xor_sync(0xffffffffu, mx, 1, 16));
            mx = fmaxf(mx, __shfl_xor_sync(0xffffffffu, mx, 2, 16));
            mx = fmaxf(mx, __shfl_xor_sync(0xffffffffu, mx, 4, 16));
            mx = fmaxf(mx, __shfl_xor_sync(0xffffffffu, mx, 8, 16));
            float mn = fmaxf(m[r], mx);
            float alpha = __expf(m[r] - mn);
            m[r] = mn;
            float rs = 0.f;
#pragma unroll
            for (int c = 0; c < 4; c++) { s[r][c] = __expf(s[r][c] - mn); rs += s[r][c]; }
            rs += __shfl_xor_sync(0xffffffffu, rs, 1, 16);
            rs += __shfl_xor_sync(0xffffffffu, rs, 2, 16);
            rs += __shfl_xor_sync(0xffffffffu, rs, 4, 16);
            rs += __shfl_xor_sync(0xffffffffu, rs, 8, 16);
            l[r] = l[r] * alpha + rs;
            unsigned long long ap = pack2(alpha, alpha);
            acc[r][0] = fmul2(acc[r][0], ap);
            acc[r][1] = fmul2(acc[r][1], ap);
            *(float4*)&Ps[(ty*4+r)*64 + tx*4] = make_float4(s[r][0],s[r][1],s[r][2],s[r][3]);
        }
        __syncthreads();

#pragma unroll 4
        for (int j = 0; j < 64; j++) {
            ulonglong2 vp = *(const ulonglong2*)&Vs[j*64 + tx*4];
#pragma unroll
            for (int r = 0; r < 4; r++) {
                float p = Ps[(ty*4+r)*64 + j];
                unsigned long long pd = pack2(p, p);
                acc[r][0] = ffma2(pd, vp.x, acc[r][0]);
                acc[r][1] = ffma2(pd, vp.y, acc[r][1]);
            }
        }
    }

#pragma unroll
    for (int r = 0; r < 4; r++) {
        float inv = 1.0f / l[r];
        float o[4];
        unpack2(acc[r][0], o[0], o[1]);
        unpack2(acc[r][1], o[2], o[3]);
        float* yrow = Y + baseoff + (size_t)(q0 + ty*4 + r) * EDIM + tx*4;
        *(float4*)yrow = make_float4(o[0]*inv, o[1]*inv, o[2]*inv, o[3]*inv);
    }
}

// ---------------- launch ----------------
extern "C" void kernel_launch(void* const* d_in, const int* in_sizes, int n_in,
                              void* d_out, int out_size)
{
    const float* x  = (const float*)d_in[0];
    const float* Wq = (const float*)d_in[1];
    const float* Wk = (const float*)d_in[2];
    const float* Wv = (const float*)d_in[3];
    const float* Wo = (const float*)d_in[4];
    const float* bq = (const float*)d_in[5];
    const float* bk = (const float*)d_in[6];
    const float* bv = (const float*)d_in[7];
    const float* bo = (const float*)d_in[8];

    float *q, *k, *v, *y;
    __nv_bfloat16 *xh, *xl, *yh, *yl, *wh, *wl;
    cudaGetSymbolAddress((void**)&q,  g_q);
    cudaGetSymbolAddress((void**)&k,  g_k);
    cudaGetSymbolAddress((void**)&v,  g_v);
    cudaGetSymbolAddress((void**)&y,  g_y);
    cudaGetSymbolAddress((void**)&xh, g_xh);
    cudaGetSymbolAddress((void**)&xl, g_xl);
    cudaGetSymbolAddress((void**)&yh, g_yh);
    cudaGetSymbolAddress((void**)&yl, g_yl);
    cudaGetSymbolAddress((void**)&wh, g_wh);
    cudaGetSymbolAddress((void**)&wl, g_wl);

    static bool attr_done = false;
    if (!attr_done) {
        cudaFuncSetAttribute(gemm_tc3, cudaFuncAttributeMaxDynamicSharedMemorySize, GEMM_SMEM);
        cudaFuncSetAttribute(swattn,   cudaFuncAttributeMaxDynamicSharedMemorySize, 65536);
        attr_done = true;
    }

    const int NX4 = MROWS * EDIM / 4;
    const int NW4 = EDIM * EDIM / 4;
    const size_t WSZ = (size_t)EDIM * EDIM;

    split_bf16<<<(NX4 + 255) / 256, 256>>>(x, xh, xl, NX4);
    split_bf16<<<(NW4 + 255) / 256, 256>>>(Wq, wh + 0*WSZ, wl + 0*WSZ, NW4);
    split_bf16<<<(NW4 + 255) / 256, 256>>>(Wk, wh + 1*WSZ, wl + 1*WSZ, NW4);
    split_bf16<<<(NW4 + 255) / 256, 256>>>(Wv, wh + 2*WSZ, wl + 2*WSZ, NW4);
    split_bf16<<<(NW4 + 255) / 256, 256>>>(Wo, wh + 3*WSZ, wl + 3*WSZ, NW4);

    // fused Q/K/V projection: grid.z = 3
    gemm_tc3<<<dim3(EDIM/BN, MROWS/BM, 3), 256, GEMM_SMEM>>>(
        xh, xl, wh, wl, bq, bk, bv, q, k, v, 0.125f);

    swattn<<<dim3(SEQ/64, HEADS, BATCH), 256, 65536>>>(q, k, v, y);

    split_bf16<<<(NX4 + 255) / 256, 256>>>(y, yh, yl, NX4);

    // output projection: z-dim 1, weights slab 3
    gemm_tc3<<<dim3(EDIM/BN, MROWS/BM, 1), 256, GEMM_SMEM>>>(
        yh, yl, wh + 3*WSZ, wl + 3*WSZ, bo, nullptr, nullptr,
        (float*)d_out, nullptr, nullptr, 1.0f);
}

// round 5
// speedup vs baseline: 2.3009x; 1.2076x over previous
#include <cuda_runtime.h>
#include <cuda_bf16.h>
#include <cstdint>

#define EDIM  1024
#define HEADS 16
#define HD    64
#define WIN   256
#define BATCH 2
#define SEQ   2048
#define MROWS (BATCH*SEQ)   // 4096

// ---------------- scratch (allocation-free rule: device globals) ----------------
static __device__ __nv_bfloat16 g_xh[MROWS*EDIM];
static __device__ __nv_bfloat16 g_xl[MROWS*EDIM];
static __device__ __nv_bfloat16 g_qh[MROWS*EDIM];
static __device__ __nv_bfloat16 g_ql[MROWS*EDIM];
static __device__ __nv_bfloat16 g_kh[MROWS*EDIM];
static __device__ __nv_bfloat16 g_kl[MROWS*EDIM];
static __device__ __nv_bfloat16 g_vh[MROWS*EDIM];
static __device__ __nv_bfloat16 g_vl[MROWS*EDIM];
static __device__ __nv_bfloat16 g_yh[MROWS*EDIM];
static __device__ __nv_bfloat16 g_yl[MROWS*EDIM];
static __device__ __nv_bfloat16 g_wh[4][EDIM*EDIM];
static __device__ __nv_bfloat16 g_wl[4][EDIM*EDIM];

// ---------------- family-common PTX helpers ----------------
__device__ __forceinline__ uint32_t smem_to_u32(const void* p) {
    uint32_t a;
    asm("{ .reg .u64 t; cvta.to.shared.u64 t, %1; cvt.u32.u64 %0, t; }"
        : "=r"(a) : "l"(p));
    return a;
}
__device__ __forceinline__ void cp_async16(uint32_t dst, const void* src) {
    asm volatile("cp.async.cg.shared.global [%0], [%1], 16;" :: "r"(dst), "l"(src));
}
#define CP_COMMIT() asm volatile("cp.async.commit_group;" ::: "memory")
#define CP_WAIT1()  asm volatile("cp.async.wait_group 1;" ::: "memory")
#define CP_WAIT0()  asm volatile("cp.async.wait_group 0;" ::: "memory")

__device__ __forceinline__ void ldsm4(uint32_t& r0, uint32_t& r1, uint32_t& r2,
                                      uint32_t& r3, uint32_t addr) {
    asm volatile("ldmatrix.sync.aligned.m8n8.x4.shared.b16 {%0,%1,%2,%3}, [%4];"
                 : "=r"(r0), "=r"(r1), "=r"(r2), "=r"(r3) : "r"(addr));
}
__device__ __forceinline__ void ldsm4t(uint32_t& r0, uint32_t& r1, uint32_t& r2,
                                       uint32_t& r3, uint32_t addr) {
    asm volatile("ldmatrix.sync.aligned.m8n8.x4.trans.shared.b16 {%0,%1,%2,%3}, [%4];"
                 : "=r"(r0), "=r"(r1), "=r"(r2), "=r"(r3) : "r"(addr));
}
__device__ __forceinline__ void mma16816(float* c, uint32_t a0, uint32_t a1,
                                         uint32_t a2, uint32_t a3,
                                         uint32_t b0, uint32_t b1) {
    asm volatile(
        "mma.sync.aligned.m16n8k16.row.col.f32.bf16.bf16.f32 "
        "{%0,%1,%2,%3}, {%4,%5,%6,%7}, {%8,%9}, {%0,%1,%2,%3};"
        : "+f"(c[0]), "+f"(c[1]), "+f"(c[2]), "+f"(c[3])
        : "r"(a0), "r"(a1), "r"(a2), "r"(a3), "r"(b0), "r"(b1));
}
__device__ __forceinline__ uint32_t packbf2(float a, float b) {
    __nv_bfloat162 t = __floats2bfloat162_rn(a, b);
    return *(uint32_t*)&t;
}

// ---------------- fp32 -> bf16 hi/lo split ----------------
__global__ __launch_bounds__(256)
void split_bf16(const float* __restrict__ in, __nv_bfloat16* __restrict__ hi,
                __nv_bfloat16* __restrict__ lo, int n4)
{
    int i = blockIdx.x * 256 + threadIdx.x;
    if (i >= n4) return;
    float4 v = ((const float4*)in)[i];
    float vv[4] = {v.x, v.y, v.z, v.w};
    __nv_bfloat16 h[4], l[4];
#pragma unroll
    for (int j = 0; j < 4; j++) {
        h[j] = __float2bfloat16_rn(vv[j]);
        l[j] = __float2bfloat16_rn(vv[j] - __bfloat162float(h[j]));
    }
    ((uint2*)hi)[i] = *(uint2*)h;
    ((uint2*)lo)[i] = *(uint2*)l;
}

// ---------------- bf16 warp-MMA GEMM, 3-segment split-K ----------------
#define BM   128
#define BN   128
#define BKC  64
#define LDSB 72
#define ATILE (BM*LDSB)
#define BTILE (BN*LDSB)
#define GEMM_SMEM (3*(ATILE+BTILE)*2)

__global__ __launch_bounds__(256)
void gemm_tc3(const __nv_bfloat16* __restrict__ Ah, const __nv_bfloat16* __restrict__ Al,
              const __nv_bfloat16* __restrict__ Wh, const __nv_bfloat16* __restrict__ Wl,
              const float* __restrict__ b0v, const float* __restrict__ b1v,
              const float* __restrict__ b2v,
              float* __restrict__ Cf,
              __nv_bfloat16* __restrict__ H0, __nv_bfloat16* __restrict__ L0,
              __nv_bfloat16* __restrict__ H1, __nv_bfloat16* __restrict__ L1,
              __nv_bfloat16* __restrict__ H2, __nv_bfloat16* __restrict__ L2,
              float s0, int bf16out)
{
    extern __shared__ __align__(16) __nv_bfloat16 gsm[];
    __nv_bfloat16* As = gsm;
    __nv_bfloat16* Bs = gsm + 3 * ATILE;

    const int tid  = threadIdx.x;
    const int wid  = tid >> 5;
    const int lane = tid & 31;
    const int bm   = blockIdx.y * BM;
    const int bn   = blockIdx.x * BN;
    const int z    = blockIdx.z;
    const int wm   = (wid & 3) * 32;
    const int wn   = (wid >> 2) * 64;

    const __nv_bfloat16* Bh = Wh + (size_t)z * EDIM * EDIM + (size_t)bn * EDIM;
    const __nv_bfloat16* Bl = Wl + (size_t)z * EDIM * EDIM + (size_t)bn * EDIM;
    const __nv_bfloat16* Ahb = Ah + (size_t)bm * EDIM;
    const __nv_bfloat16* Alb = Al + (size_t)bm * EDIM;
    const float* bias = (z == 0) ? b0v : (z == 1) ? b1v : b2v;
    const float scale = (z == 0) ? s0 : 1.0f;

    const __nv_bfloat16* segA[3] = {Ahb, Ahb, Alb};
    const __nv_bfloat16* segB[3] = {Bh,  Bl,  Bh};

    float acc[2][8][4];
#pragma unroll
    for (int mt = 0; mt < 2; mt++)
#pragma unroll
        for (int nt = 0; nt < 8; nt++)
#pragma unroll
            for (int j = 0; j < 4; j++) acc[mt][nt][j] = 0.f;

    const int a_row = lane & 15, a_ch = lane >> 4;
    const int b_nin = (lane & 7) + ((lane >= 16) ? 8 : 0);
    const int b_ch  = (lane >> 3) & 1;

#define LOADC(cc, st) do { \
    const int _seg = (cc) >> 4, _kc = (cc) & 15; \
    const __nv_bfloat16* _a = segA[_seg] + (size_t)_kc * BKC; \
    const __nv_bfloat16* _b = segB[_seg] + (size_t)_kc * BKC; \
    __nv_bfloat16* _as = As + (st) * ATILE; \
    __nv_bfloat16* _bs = Bs + (st) * BTILE; \
    _Pragma("unroll") \
    for (int _i = 0; _i < 4; _i++) { \
        int _idx = tid + _i * 256; int _r = _idx >> 3, _s = _idx & 7; \
        cp_async16(smem_to_u32(&_as[_r * LDSB + _s * 8]), _a + (size_t)_r * EDIM + _s * 8); \
        cp_async16(smem_to_u32(&_bs[_r * LDSB + _s * 8]), _b + (size_t)_r * EDIM + _s * 8); \
    } \
} while (0)

    const int NCH = 48;
    LOADC(0, 0); CP_COMMIT();
    LOADC(1, 1); CP_COMMIT();

    for (int c = 0; c < NCH; c++) {
        CP_WAIT1();
        __syncthreads();
        if (c + 2 < NCH) { LOADC(c + 2, (c + 2) % 3); CP_COMMIT(); }

        const __nv_bfloat16* as = As + (c % 3) * ATILE;
        const __nv_bfloat16* bs = Bs + (c % 3) * BTILE;
#pragma unroll
        for (int ks = 0; ks < 4; ks++) {
            const int k0 = ks * 16;
            uint32_t a[2][4];
#pragma unroll
            for (int mt = 0; mt < 2; mt++) {
                uint32_t addr = smem_to_u32(&as[(wm + mt * 16 + a_row) * LDSB + k0 + a_ch * 8]);
                ldsm4(a[mt][0], a[mt][1], a[mt][2], a[mt][3], addr);
            }
            uint32_t b[8][2];
#pragma unroll
            for (int p = 0; p < 4; p++) {
                uint32_t r0, r1, r2, r3;
                uint32_t addr = smem_to_u32(&bs[(wn + p * 16 + b_nin) * LDSB + k0 + b_ch * 8]);
                ldsm4(r0, r1, r2, r3, addr);
                b[2 * p][0] = r0;     b[2 * p][1] = r1;
                b[2 * p + 1][0] = r2; b[2 * p + 1][1] = r3;
            }
#pragma unroll
            for (int mt = 0; mt < 2; mt++)
#pragma unroll
                for (int nt = 0; nt < 8; nt++)
                    mma16816(acc[mt][nt], a[mt][0], a[mt][1], a[mt][2], a[mt][3],
                             b[nt][0], b[nt][1]);
        }
    }
#undef LOADC

    if (bf16out) {
        __nv_bfloat16* H = (z == 0) ? H0 : (z == 1) ? H1 : H2;
        __nv_bfloat16* L = (z == 0) ? L0 : (z == 1) ? L1 : L2;
#pragma unroll
        for (int nt = 0; nt < 8; nt++) {
            const int col = bn + wn + nt * 8 + (lane & 3) * 2;
            const float c0 = bias[col], c1 = bias[col + 1];
#pragma unroll
            for (int mt = 0; mt < 2; mt++) {
                const int r0 = bm + wm + mt * 16 + (lane >> 2);
#pragma unroll
                for (int rr = 0; rr < 2; rr++) {
                    float vx = (acc[mt][nt][2*rr+0] + c0) * scale;
                    float vy = (acc[mt][nt][2*rr+1] + c1) * scale;
                    __nv_bfloat16 hx = __float2bfloat16_rn(vx);
                    __nv_bfloat16 hy = __float2bfloat16_rn(vy);
                    float lx = vx - __bfloat162float(hx);
                    float ly = vy - __bfloat162float(hy);
                    size_t off = (size_t)(r0 + rr*8) * EDIM + col;
                    *(uint32_t*)(H + off) = ((uint32_t)*(uint16_t*)&hy << 16) | *(uint16_t*)&hx;
                    *(uint32_t*)(L + off) = packbf2(lx, ly);
                }
            }
        }
    } else {
#pragma unroll
        for (int nt = 0; nt < 8; nt++) {
            const int col = bn + wn + nt * 8 + (lane & 3) * 2;
            const float c0 = bias[col], c1 = bias[col + 1];
#pragma unroll
            for (int mt = 0; mt < 2; mt++) {
                const int r0 = bm + wm + mt * 16 + (lane >> 2);
                *(float2*)&Cf[(size_t)r0 * EDIM + col] =
                    make_float2((acc[mt][nt][0] + c0) * scale, (acc[mt][nt][1] + c1) * scale);
                *(float2*)&Cf[(size_t)(r0 + 8) * EDIM + col] =
                    make_float2((acc[mt][nt][2] + c0) * scale, (acc[mt][nt][3] + c1) * scale);
            }
        }
    }
}

// ---------------- sliding-window flash attention, bf16-split warp MMA ----------------
#define ALDA 72
#define ATT_SMEM ((2*64 + 2*4*64) * ALDA * 2)   // Q(h,l) + 2 bufs x (kh,kl,vh,vl) = 92160 B

__global__ __launch_bounds__(128)
void swattn_tc(const __nv_bfloat16* __restrict__ Qh, const __nv_bfloat16* __restrict__ Ql,
               const __nv_bfloat16* __restrict__ Kh, const __nv_bfloat16* __restrict__ Kl,
               const __nv_bfloat16* __restrict__ Vh, const __nv_bfloat16* __restrict__ Vl,
               __nv_bfloat16* __restrict__ Oh, __nv_bfloat16* __restrict__ Ol)
{
    extern __shared__ __align__(16) __nv_bfloat16 sb[];
    __nv_bfloat16* Qsh = sb;
    __nv_bfloat16* Qsl = Qsh + 64 * ALDA;
    __nv_bfloat16* KV  = Qsl + 64 * ALDA;     // [buf][4][64*ALDA]

    const int tid = threadIdx.x, wid = tid >> 5, lane = tid & 31;
    const int qt = blockIdx.x, h = blockIdx.y, b = blockIdx.z;
    const int q0 = qt * 64;
    const size_t base = (size_t)b * SEQ * EDIM + (size_t)h * HD;
    const int kb0 = (qt > 4) ? qt - 4 : 0;
    const int NB  = qt - kb0 + 1;

    // Q load (2 tensors x 64 rows x 8 segs)
    {
        const __nv_bfloat16* qs[2] = {Qh, Ql};
        __nv_bfloat16* qd[2] = {Qsh, Qsl};
#pragma unroll
        for (int i = 0; i < 8; i++) {
            int idx = tid + i * 128;
            int t = idx >> 9, r = (idx >> 3) & 63, s = idx & 7;
            cp_async16(smem_to_u32(qd[t] + r * ALDA + s * 8),
                       qs[t] + base + (size_t)(q0 + r) * EDIM + s * 8);
        }
    }
    CP_COMMIT();

#define ALOAD_KV(kb, buf) do { \
    const __nv_bfloat16* _srcs[4] = {Kh, Kl, Vh, Vl}; \
    __nv_bfloat16* _d = KV + (buf) * 4 * 64 * ALDA; \
    _Pragma("unroll") \
    for (int _i = 0; _i < 16; _i++) { \
        int _idx = tid + _i * 128; \
        int _t = _idx >> 9, _r = (_idx >> 3) & 63, _s = _idx & 7; \
        cp_async16(smem_to_u32(_d + _t * 64 * ALDA + _r * ALDA + _s * 8), \
                   _srcs[_t] + base + (size_t)((kb) * 64 + _r) * EDIM + _s * 8); \
    } \
} while (0)

    ALOAD_KV(kb0, 0); CP_COMMIT();
    if (NB >= 2) { ALOAD_KV(kb0 + 1, 1); CP_COMMIT(); }

    const int b_nin = (lane & 7) + ((lane >= 16) ? 8 : 0);
    const int b_ch  = (lane >> 3) & 1;

    uint32_t qhf[4][4], qlf[4][4];
    float o[8][4];
#pragma unroll
    for (int nt = 0; nt < 8; nt++)
#pragma unroll
        for (int j = 0; j < 4; j++) o[nt][j] = 0.f;
    float m0 = -1e30f, m1 = -1e30f, l0 = 0.f, l1 = 0.f;
    const int i0 = q0 + wid * 16 + (lane >> 2);

    for (int j = 0; j < NB; j++) {
        if (j + 1 < NB) CP_WAIT1(); else CP_WAIT0();
        __syncthreads();
        if (j == 0) {
#pragma unroll
            for (int kt = 0; kt < 4; kt++) {
                uint32_t ah = smem_to_u32(&Qsh[(wid*16 + (lane & 15)) * ALDA + kt*16 + (lane >> 4)*8]);
                uint32_t al = smem_to_u32(&Qsl[(wid*16 + (lane & 15)) * ALDA + kt*16 + (lane >> 4)*8]);
                ldsm4(qhf[kt][0], qhf[kt][1], qhf[kt][2], qhf[kt][3], ah);
                ldsm4(qlf[kt][0], qlf[kt][1], qlf[kt][2], qlf[kt][3], al);
            }
        }
        const int kb = kb0 + j;
        const __nv_bfloat16* khs = KV + (j & 1) * 4 * 64 * ALDA;
        const __nv_bfloat16* kls = khs + 64 * ALDA;
        const __nv_bfloat16* vhs = khs + 2 * 64 * ALDA;
        const __nv_bfloat16* vls = khs + 3 * 64 * ALDA;

        // ---- S = Qh Kh + Qh Kl + Ql Kh ----
        float s[8][4];
#pragma unroll
        for (int nt = 0; nt < 8; nt++)
#pragma unroll
            for (int c = 0; c < 4; c++) s[nt][c] = 0.f;

#pragma unroll
        for (int kt = 0; kt < 4; kt++) {
            uint32_t bh[8][2], bl[8][2];
#pragma unroll
            for (int p = 0; p < 4; p++) {
                uint32_t r0, r1, r2, r3;
                uint32_t addr = smem_to_u32(&khs[(p*16 + b_nin) * ALDA + kt*16 + b_ch*8]);
                ldsm4(r0, r1, r2, r3, addr);
                bh[2*p][0] = r0; bh[2*p][1] = r1; bh[2*p+1][0] = r2; bh[2*p+1][1] = r3;
                addr = smem_to_u32(&kls[(p*16 + b_nin) * ALDA + kt*16 + b_ch*8]);
                ldsm4(r0, r1, r2, r3, addr);
                bl[2*p][0] = r0; bl[2*p][1] = r1; bl[2*p+1][0] = r2; bl[2*p+1][1] = r3;
            }
#pragma unroll
            for (int nt = 0; nt < 8; nt++) {
                mma16816(s[nt], qhf[kt][0], qhf[kt][1], qhf[kt][2], qhf[kt][3], bh[nt][0], bh[nt][1]);
                mma16816(s[nt], qhf[kt][0], qhf[kt][1], qhf[kt][2], qhf[kt][3], bl[nt][0], bl[nt][1]);
                mma16816(s[nt], qlf[kt][0], qlf[kt][1], qlf[kt][2], qlf[kt][3], bh[nt][0], bh[nt][1]);
            }
        }

        // ---- mask + online softmax ----
        float mxA = -1e30f, mxB = -1e30f;
#pragma unroll
        for (int nt = 0; nt < 8; nt++) {
            int jb = kb * 64 + nt * 8 + (lane & 3) * 2;
            int d0 = i0 - jb;
            if ((unsigned)d0       > 256u) s[nt][0] = -1e30f;
            if ((unsigned)(d0 - 1) > 256u) s[nt][1] = -1e30f;
            if ((unsigned)(d0 + 8) > 256u) s[nt][2] = -1e30f;
            if ((unsigned)(d0 + 7) > 256u) s[nt][3] = -1e30f;
            mxA = fmaxf(mxA, fmaxf(s[nt][0], s[nt][1]));
            mxB = fmaxf(mxB, fmaxf(s[nt][2], s[nt][3]));
        }
        mxA = fmaxf(mxA, __shfl_xor_sync(0xffffffffu, mxA, 1));
        mxA = fmaxf(mxA, __shfl_xor_sync(0xffffffffu, mxA, 2));
        mxB = fmaxf(mxB, __shfl_xor_sync(0xffffffffu, mxB, 1));
        mxB = fmaxf(mxB, __shfl_xor_sync(0xffffffffu, mxB, 2));
        float nm0 = fmaxf(m0, mxA), nm1 = fmaxf(m1, mxB);
        float al0 = __expf(m0 - nm0), al1 = __expf(m1 - nm1);
        m0 = nm0; m1 = nm1;
        float rs0 = 0.f, rs1 = 0.f;
#pragma unroll
        for (int nt = 0; nt < 8; nt++) {
            s[nt][0] = __expf(s[nt][0] - m0);
            s[nt][1] = __expf(s[nt][1] - m0);
            s[nt][2] = __expf(s[nt][2] - m1);
            s[nt][3] = __expf(s[nt][3] - m1);
            rs0 += s[nt][0] + s[nt][1];
            rs1 += s[nt][2] + s[nt][3];
            o[nt][0] *= al0; o[nt][1] *= al0; o[nt][2] *= al1; o[nt][3] *= al1;
        }
        rs0 += __shfl_xor_sync(0xffffffffu, rs0, 1);
        rs0 += __shfl_xor_sync(0xffffffffu, rs0, 2);
        rs1 += __shfl_xor_sync(0xffffffffu, rs1, 1);
        rs1 += __shfl_xor_sync(0xffffffffu, rs1, 2);
        l0 = l0 * al0 + rs0;
        l1 = l1 * al1 + rs1;

        // ---- O += (Ph+Pl) @ (Vh+Vl)  (3 passes) ----
#pragma unroll
        for (int kt = 0; kt < 4; kt++) {
            // P fragments from S accumulators (layout identity)
            uint32_t pha[4], pla[4];
            {
                const int t0 = 2 * kt, t1 = 2 * kt + 1;
                __nv_bfloat16 h00 = __float2bfloat16_rn(s[t0][0]);
                __nv_bfloat16 h01 = __float2bfloat16_rn(s[t0][1]);
                __nv_bfloat16 h02 = __float2bfloat16_rn(s[t0][2]);
                __nv_bfloat16 h03 = __float2bfloat16_rn(s[t0][3]);
                __nv_bfloat16 h10 = __float2bfloat16_rn(s[t1][0]);
                __nv_bfloat16 h11 = __float2bfloat16_rn(s[t1][1]);
                __nv_bfloat16 h12 = __float2bfloat16_rn(s[t1][2]);
                __nv_bfloat16 h13 = __float2bfloat16_rn(s[t1][3]);
                pha[0] = ((uint32_t)*(uint16_t*)&h01 << 16) | *(uint16_t*)&h00;
                pha[1] = ((uint32_t)*(uint16_t*)&h03 << 16) | *(uint16_t*)&h02;
                pha[2] = ((uint32_t)*(uint16_t*)&h11 << 16) | *(uint16_t*)&h10;
                pha[3] = ((uint32_t)*(uint16_t*)&h13 << 16) | *(uint16_t*)&h12;
                pla[0] = packbf2(s[t0][0] - __bfloat162float(h00), s[t0][1] - __bfloat162float(h01));
                pla[1] = packbf2(s[t0][2] - __bfloat162float(h02), s[t0][3] - __bfloat162float(h03));
                pla[2] = packbf2(s[t1][0] - __bfloat162float(h10), s[t1][1] - __bfloat162float(h11));
                pla[3] = packbf2(s[t1][2] - __bfloat162float(h12), s[t1][3] - __bfloat162float(h13));
            }
#pragma unroll
            for (int p = 0; p < 4; p++) {
                uint32_t vrow = (kt*16 + ((lane >> 3) & 1)*8 + (lane & 7)) * ALDA + (p*2 + (lane >> 4))*8;
                uint32_t r0, r1, r2, r3, t0, t1, t2, t3;
                ldsm4t(r0, r1, r2, r3, smem_to_u32(&vhs[vrow]));
                ldsm4t(t0, t1, t2, t3, smem_to_u32(&vls[vrow]));
                mma16816(o[2*p],   pha[0], pha[1], pha[2], pha[3], r0, r1);
                mma16816(o[2*p],   pha[0], pha[1], pha[2], pha[3], t0, t1);
                mma16816(o[2*p],   pla[0], pla[1], pla[2], pla[3], r0, r1);
                mma16816(o[2*p+1], pha[0], pha[1], pha[2], pha[3], r2, r3);
                mma16816(o[2*p+1], pha[0], pha[1], pha[2], pha[3], t2, t3);
                mma16816(o[2*p+1], pla[0], pla[1], pla[2], pla[3], r2, r3);
            }
        }

        __syncthreads();
        if (j + 2 < NB) { ALOAD_KV(kb0 + j + 2, j & 1); CP_COMMIT(); }
    }
#undef ALOAD_KV

    // ---- epilogue: O /= l, write bf16 hi/lo ----
    const float inv0 = 1.0f / l0, inv1 = 1.0f / l1;
#pragma unroll
    for (int nt = 0; nt < 8; nt++) {
        const int col = nt * 8 + (lane & 3) * 2;
        float v0 = o[nt][0] * inv0, v1 = o[nt][1] * inv0;
        float v2 = o[nt][2] * inv1, v3 = o[nt][3] * inv1;
        __nv_bfloat16 h0 = __float2bfloat16_rn(v0), h1 = __float2bfloat16_rn(v1);
        __nv_bfloat16 h2 = __float2bfloat16_rn(v2), h3 = __float2bfloat16_rn(v3);
        size_t off0 = base + (size_t)i0 * EDIM + col;
        size_t off1 = base + (size_t)(i0 + 8) * EDIM + col;
        *(uint32_t*)(Oh + off0) = ((uint32_t)*(uint16_t*)&h1 << 16) | *(uint16_t*)&h0;
        *(uint32_t*)(Oh + off1) = ((uint32_t)*(uint16_t*)&h3 << 16) | *(uint16_t*)&h2;
        *(uint32_t*)(Ol + off0) = packbf2(v0 - __bfloat162float(h0), v1 - __bfloat162float(h1));
        *(uint32_t*)(Ol + off1) = packbf2(v2 - __bfloat162float(h2), v3 - __bfloat162float(h3));
    }
}

// ---------------- launch ----------------
extern "C" void kernel_launch(void* const* d_in, const int* in_sizes, int n_in,
                              void* d_out, int out_size)
{
    const float* x  = (const float*)d_in[0];
    const float* Wq = (const float*)d_in[1];
    const float* Wk = (const float*)d_in[2];
    const float* Wv = (const float*)d_in[3];
    const float* Wo = (const float*)d_in[4];
    const float* bq = (const float*)d_in[5];
    const float* bk = (const float*)d_in[6];
    const float* bv = (const float*)d_in[7];
    const float* bo = (const float*)d_in[8];

    __nv_bfloat16 *xh, *xl, *qh, *ql, *kh, *kl, *vh, *vl, *yh, *yl, *wh, *wl;
    cudaGetSymbolAddress((void**)&xh, g_xh);
    cudaGetSymbolAddress((void**)&xl, g_xl);
    cudaGetSymbolAddress((void**)&qh, g_qh);
    cudaGetSymbolAddress((void**)&ql, g_ql);
    cudaGetSymbolAddress((void**)&kh, g_kh);
    cudaGetSymbolAddress((void**)&kl, g_kl);
    cudaGetSymbolAddress((void**)&vh, g_vh);
    cudaGetSymbolAddress((void**)&vl, g_vl);
    cudaGetSymbolAddress((void**)&yh, g_yh);
    cudaGetSymbolAddress((void**)&yl, g_yl);
    cudaGetSymbolAddress((void**)&wh, g_wh);
    cudaGetSymbolAddress((void**)&wl, g_wl);

    static bool attr_done = false;
    if (!attr_done) {
        cudaFuncSetAttribute(gemm_tc3,  cudaFuncAttributeMaxDynamicSharedMemorySize, GEMM_SMEM);
        cudaFuncSetAttribute(swattn_tc, cudaFuncAttributeMaxDynamicSharedMemorySize, ATT_SMEM);
        attr_done = true;
    }

    const int NX4 = MROWS * EDIM / 4;
    const int NW4 = EDIM * EDIM / 4;
    const size_t WSZ = (size_t)EDIM * EDIM;

    split_bf16<<<(NX4 + 255) / 256, 256>>>(x, xh, xl, NX4);
    split_bf16<<<(NW4 + 255) / 256, 256>>>(Wq, wh + 0*WSZ, wl + 0*WSZ, NW4);
    split_bf16<<<(NW4 + 255) / 256, 256>>>(Wk, wh + 1*WSZ, wl + 1*WSZ, NW4);
    split_bf16<<<(NW4 + 255) / 256, 256>>>(Wv, wh + 2*WSZ, wl + 2*WSZ, NW4);
    split_bf16<<<(NW4 + 255) / 256, 256>>>(Wo, wh + 3*WSZ, wl + 3*WSZ, NW4);

    // fused QKV projection -> bf16 hi/lo outputs (q pre-scaled by 1/8)
    gemm_tc3<<<dim3(EDIM/BN, MROWS/BM, 3), 256, GEMM_SMEM>>>(
        xh, xl, wh, wl, bq, bk, bv, nullptr,
        qh, ql, kh, kl, vh, vl, 0.125f, 1);

    swattn_tc<<<dim3(SEQ/64, HEADS, BATCH), 128, ATT_SMEM>>>(
        qh, ql, kh, kl, vh, vl, yh, yl);

    // output projection -> fp32 d_out
    gemm_tc3<<<dim3(EDIM/BN, MROWS/BM, 1), 256, GEMM_SMEM>>>(
        yh, yl, wh + 3*WSZ, wl + 3*WSZ, bo, nullptr, nullptr,
        (float*)d_out, nullptr, nullptr, nullptr, nullptr, nullptr, nullptr, 1.0f, 0);
}

// round 6
// speedup vs baseline: 2.3735x; 1.0316x over previous
#include <cuda_runtime.h>
#include <cuda_bf16.h>
#include <cstdint>

#define EDIM  1024
#define HEADS 16
#define HD    64
#define WIN   256
#define BATCH 2
#define SEQ   2048
#define MROWS (BATCH*SEQ)   // 4096

// ---------------- scratch (allocation-free rule: device globals) ----------------
static __device__ __nv_bfloat16 g_xh[MROWS*EDIM];
static __device__ __nv_bfloat16 g_xl[MROWS*EDIM];
static __device__ __nv_bfloat16 g_qh[MROWS*EDIM];
static __device__ __nv_bfloat16 g_ql[MROWS*EDIM];
static __device__ __nv_bfloat16 g_kh[MROWS*EDIM];
static __device__ __nv_bfloat16 g_kl[MROWS*EDIM];
static __device__ __nv_bfloat16 g_vh[MROWS*EDIM];
static __device__ __nv_bfloat16 g_vl[MROWS*EDIM];
static __device__ __nv_bfloat16 g_yh[MROWS*EDIM];
static __device__ __nv_bfloat16 g_yl[MROWS*EDIM];
static __device__ __nv_bfloat16 g_wh[4][EDIM*EDIM];
static __device__ __nv_bfloat16 g_wl[4][EDIM*EDIM];

// ---------------- family-common PTX helpers ----------------
__device__ __forceinline__ uint32_t smem_to_u32(const void* p) {
    uint32_t a;
    asm("{ .reg .u64 t; cvta.to.shared.u64 t, %1; cvt.u32.u64 %0, t; }"
        : "=r"(a) : "l"(p));
    return a;
}
__device__ __forceinline__ void cp_async16(uint32_t dst, const void* src) {
    asm volatile("cp.async.cg.shared.global [%0], [%1], 16;" :: "r"(dst), "l"(src));
}
#define CP_COMMIT() asm volatile("cp.async.commit_group;" ::: "memory")
#define CP_WAIT1()  asm volatile("cp.async.wait_group 1;" ::: "memory")
#define CP_WAIT0()  asm volatile("cp.async.wait_group 0;" ::: "memory")

__device__ __forceinline__ void ldsm4(uint32_t& r0, uint32_t& r1, uint32_t& r2,
                                      uint32_t& r3, uint32_t addr) {
    asm volatile("ldmatrix.sync.aligned.m8n8.x4.shared.b16 {%0,%1,%2,%3}, [%4];"
                 : "=r"(r0), "=r"(r1), "=r"(r2), "=r"(r3) : "r"(addr));
}
__device__ __forceinline__ void ldsm4t(uint32_t& r0, uint32_t& r1, uint32_t& r2,
                                       uint32_t& r3, uint32_t addr) {
    asm volatile("ldmatrix.sync.aligned.m8n8.x4.trans.shared.b16 {%0,%1,%2,%3}, [%4];"
                 : "=r"(r0), "=r"(r1), "=r"(r2), "=r"(r3) : "r"(addr));
}
__device__ __forceinline__ void mma16816(float* c, uint32_t a0, uint32_t a1,
                                         uint32_t a2, uint32_t a3,
                                         uint32_t b0, uint32_t b1) {
    asm volatile(
        "mma.sync.aligned.m16n8k16.row.col.f32.bf16.bf16.f32 "
        "{%0,%1,%2,%3}, {%4,%5,%6,%7}, {%8,%9}, {%0,%1,%2,%3};"
        : "+f"(c[0]), "+f"(c[1]), "+f"(c[2]), "+f"(c[3])
        : "r"(a0), "r"(a1), "r"(a2), "r"(a3), "r"(b0), "r"(b1));
}
__device__ __forceinline__ uint32_t packbf2(float a, float b) {
    __nv_bfloat162 t = __floats2bfloat162_rn(a, b);
    return *(uint32_t*)&t;
}

// ---------------- fused fp32 -> bf16 hi/lo split (5 tensors, one launch) -------
__global__ __launch_bounds__(256)
void split5(const float* __restrict__ s0, const float* __restrict__ s1,
            const float* __restrict__ s2, const float* __restrict__ s3,
            const float* __restrict__ s4,
            __nv_bfloat16* __restrict__ h0, __nv_bfloat16* __restrict__ l0,
            __nv_bfloat16* __restrict__ h1, __nv_bfloat16* __restrict__ l1,
            __nv_bfloat16* __restrict__ h2, __nv_bfloat16* __restrict__ l2,
            __nv_bfloat16* __restrict__ h3, __nv_bfloat16* __restrict__ l3,
            __nv_bfloat16* __restrict__ h4, __nv_bfloat16* __restrict__ l4,
            int n0, int nw)
{
    const int t = blockIdx.y;
    const int n4 = (t == 0) ? n0 : nw;
    int i = blockIdx.x * 256 + threadIdx.x;
    if (i >= n4) return;
    const float* in = (t == 0) ? s0 : (t == 1) ? s1 : (t == 2) ? s2 : (t == 3) ? s3 : s4;
    __nv_bfloat16* hi = (t == 0) ? h0 : (t == 1) ? h1 : (t == 2) ? h2 : (t == 3) ? h3 : h4;
    __nv_bfloat16* lo = (t == 0) ? l0 : (t == 1) ? l1 : (t == 2) ? l2 : (t == 3) ? l3 : l4;
    float4 v = ((const float4*)in)[i];
    float vv[4] = {v.x, v.y, v.z, v.w};
    __nv_bfloat16 h[4], l[4];
#pragma unroll
    for (int j = 0; j < 4; j++) {
        h[j] = __float2bfloat16_rn(vv[j]);
        l[j] = __float2bfloat16_rn(vv[j] - __bfloat162float(h[j]));
    }
    ((uint2*)hi)[i] = *(uint2*)h;
    ((uint2*)lo)[i] = *(uint2*)l;
}

// ---------------- bf16 warp-MMA GEMM, 3-segment split-K ----------------
#define BM   128
#define BN   128
#define BKC  64
#define LDSB 72
#define ATILE (BM*LDSB)
#define BTILE (BN*LDSB)
#define GEMM_SMEM (3*(ATILE+BTILE)*2)   // 110,592 B -> 2 CTAs/SM (221 KB < 228 KB)

__global__ __launch_bounds__(256, 2)
void gemm_tc3(const __nv_bfloat16* __restrict__ Ah, const __nv_bfloat16* __restrict__ Al,
              const __nv_bfloat16* __restrict__ Wh, const __nv_bfloat16* __restrict__ Wl,
              const float* __restrict__ b0v, const float* __restrict__ b1v,
              const float* __restrict__ b2v,
              float* __restrict__ Cf,
              __nv_bfloat16* __restrict__ H0, __nv_bfloat16* __restrict__ L0,
              __nv_bfloat16* __restrict__ H1, __nv_bfloat16* __restrict__ L1,
              __nv_bfloat16* __restrict__ H2, __nv_bfloat16* __restrict__ L2,
              float s0, int bf16out)
{
    extern __shared__ __align__(16) __nv_bfloat16 gsm[];
    __nv_bfloat16* As = gsm;
    __nv_bfloat16* Bs = gsm + 3 * ATILE;

    const int tid  = threadIdx.x;
    const int wid  = tid >> 5;
    const int lane = tid & 31;
    const int bm   = blockIdx.y * BM;
    const int bn   = blockIdx.x * BN;
    const int z    = blockIdx.z;
    const int wm   = (wid & 3) * 32;
    const int wn   = (wid >> 2) * 64;

    const __nv_bfloat16* Bh = Wh + (size_t)z * EDIM * EDIM + (size_t)bn * EDIM;
    const __nv_bfloat16* Bl = Wl + (size_t)z * EDIM * EDIM + (size_t)bn * EDIM;
    const __nv_bfloat16* Ahb = Ah + (size_t)bm * EDIM;
    const __nv_bfloat16* Alb = Al + (size_t)bm * EDIM;
    const float* bias = (z == 0) ? b0v : (z == 1) ? b1v : b2v;
    const float scale = (z == 0) ? s0 : 1.0f;

    const __nv_bfloat16* segA[3] = {Ahb, Ahb, Alb};
    const __nv_bfloat16* segB[3] = {Bh,  Bl,  Bh};

    float acc[2][8][4];
#pragma unroll
    for (int mt = 0; mt < 2; mt++)
#pragma unroll
        for (int nt = 0; nt < 8; nt++)
#pragma unroll
            for (int j = 0; j < 4; j++) acc[mt][nt][j] = 0.f;

    const int a_row = lane & 15, a_ch = lane >> 4;
    const int b_nin = (lane & 7) + ((lane >= 16) ? 8 : 0);
    const int b_ch  = (lane >> 3) & 1;

#define LOADC(cc, st) do { \
    const int _seg = (cc) >> 4, _kc = (cc) & 15; \
    const __nv_bfloat16* _a = segA[_seg] + (size_t)_kc * BKC; \
    const __nv_bfloat16* _b = segB[_seg] + (size_t)_kc * BKC; \
    __nv_bfloat16* _as = As + (st) * ATILE; \
    __nv_bfloat16* _bs = Bs + (st) * BTILE; \
    _Pragma("unroll") \
    for (int _i = 0; _i < 4; _i++) { \
        int _idx = tid + _i * 256; int _r = _idx >> 3, _s = _idx & 7; \
        cp_async16(smem_to_u32(&_as[_r * LDSB + _s * 8]), _a + (size_t)_r * EDIM + _s * 8); \
        cp_async16(smem_to_u32(&_bs[_r * LDSB + _s * 8]), _b + (size_t)_r * EDIM + _s * 8); \
    } \
} while (0)

    const int NCH = 48;
    LOADC(0, 0); CP_COMMIT();
    LOADC(1, 1); CP_COMMIT();

    for (int c = 0; c < NCH; c++) {
        CP_WAIT1();
        __syncthreads();
        if (c + 2 < NCH) { LOADC(c + 2, (c + 2) % 3); CP_COMMIT(); }

        const __nv_bfloat16* as = As + (c % 3) * ATILE;
        const __nv_bfloat16* bs = Bs + (c % 3) * BTILE;
#pragma unroll
        for (int ks = 0; ks < 4; ks++) {
            const int k0 = ks * 16;
            uint32_t a[2][4];
#pragma unroll
            for (int mt = 0; mt < 2; mt++) {
                uint32_t addr = smem_to_u32(&as[(wm + mt * 16 + a_row) * LDSB + k0 + a_ch * 8]);
                ldsm4(a[mt][0], a[mt][1], a[mt][2], a[mt][3], addr);
            }
            uint32_t b[8][2];
#pragma unroll
            for (int p = 0; p < 4; p++) {
                uint32_t r0, r1, r2, r3;
                uint32_t addr = smem_to_u32(&bs[(wn + p * 16 + b_nin) * LDSB + k0 + b_ch * 8]);
                ldsm4(r0, r1, r2, r3, addr);
                b[2 * p][0] = r0;     b[2 * p][1] = r1;
                b[2 * p + 1][0] = r2; b[2 * p + 1][1] = r3;
            }
#pragma unroll
            for (int mt = 0; mt < 2; mt++)
#pragma unroll
                for (int nt = 0; nt < 8; nt++)
                    mma16816(acc[mt][nt], a[mt][0], a[mt][1], a[mt][2], a[mt][3],
                             b[nt][0], b[nt][1]);
        }
    }
#undef LOADC

    if (bf16out) {
        __nv_bfloat16* H = (z == 0) ? H0 : (z == 1) ? H1 : H2;
        __nv_bfloat16* L = (z == 0) ? L0 : (z == 1) ? L1 : L2;
#pragma unroll
        for (int nt = 0; nt < 8; nt++) {
            const int col = bn + wn + nt * 8 + (lane & 3) * 2;
            const float c0 = bias[col], c1 = bias[col + 1];
#pragma unroll
            for (int mt = 0; mt < 2; mt++) {
                const int r0 = bm + wm + mt * 16 + (lane >> 2);
#pragma unroll
                for (int rr = 0; rr < 2; rr++) {
                    float vx = (acc[mt][nt][2*rr+0] + c0) * scale;
                    float vy = (acc[mt][nt][2*rr+1] + c1) * scale;
                    __nv_bfloat16 hx = __float2bfloat16_rn(vx);
                    __nv_bfloat16 hy = __float2bfloat16_rn(vy);
                    float lx = vx - __bfloat162float(hx);
                    float ly = vy - __bfloat162float(hy);
                    size_t off = (size_t)(r0 + rr*8) * EDIM + col;
                    *(uint32_t*)(H + off) = ((uint32_t)*(uint16_t*)&hy << 16) | *(uint16_t*)&hx;
                    *(uint32_t*)(L + off) = packbf2(lx, ly);
                }
            }
        }
    } else {
#pragma unroll
        for (int nt = 0; nt < 8; nt++) {
            const int col = bn + wn + nt * 8 + (lane & 3) * 2;
            const float c0 = bias[col], c1 = bias[col + 1];
#pragma unroll
            for (int mt = 0; mt < 2; mt++) {
                const int r0 = bm + wm + mt * 16 + (lane >> 2);
                *(float2*)&Cf[(size_t)r0 * EDIM + col] =
                    make_float2((acc[mt][nt][0] + c0) * scale, (acc[mt][nt][1] + c1) * scale);
                *(float2*)&Cf[(size_t)(r0 + 8) * EDIM + col] =
                    make_float2((acc[mt][nt][2] + c0) * scale, (acc[mt][nt][3] + c1) * scale);
            }
        }
    }
}

// ---------------- sliding-window flash attention, bf16-split warp MMA ----------------
#define ALDA 72
#define ATT_SMEM ((2*64 + 2*4*64) * ALDA * 2)   // 92160 B

__global__ __launch_bounds__(128)
void swattn_tc(const __nv_bfloat16* __restrict__ Qh, const __nv_bfloat16* __restrict__ Ql,
               const __nv_bfloat16* __restrict__ Kh, const __nv_bfloat16* __restrict__ Kl,
               const __nv_bfloat16* __restrict__ Vh, const __nv_bfloat16* __restrict__ Vl,
               __nv_bfloat16* __restrict__ Oh, __nv_bfloat16* __restrict__ Ol)
{
    extern __shared__ __align__(16) __nv_bfloat16 sb[];
    __nv_bfloat16* Qsh = sb;
    __nv_bfloat16* Qsl = Qsh + 64 * ALDA;
    __nv_bfloat16* KV  = Qsl + 64 * ALDA;     // [buf][4][64*ALDA]

    const int tid = threadIdx.x, wid = tid >> 5, lane = tid & 31;
    const int qt = blockIdx.x, h = blockIdx.y, b = blockIdx.z;
    const int q0 = qt * 64;
    const size_t base = (size_t)b * SEQ * EDIM + (size_t)h * HD;
    const int kb0 = (qt > 4) ? qt - 4 : 0;
    const int NB  = qt - kb0 + 1;

    {
        const __nv_bfloat16* qs[2] = {Qh, Ql};
        __nv_bfloat16* qd[2] = {Qsh, Qsl};
#pragma unroll
        for (int i = 0; i < 8; i++) {
            int idx = tid + i * 128;
            int t = idx >> 9, r = (idx >> 3) & 63, s = idx & 7;
            cp_async16(smem_to_u32(qd[t] + r * ALDA + s * 8),
                       qs[t] + base + (size_t)(q0 + r) * EDIM + s * 8);
        }
    }
    CP_COMMIT();

#define ALOAD_KV(kb, buf) do { \
    const __nv_bfloat16* _srcs[4] = {Kh, Kl, Vh, Vl}; \
    __nv_bfloat16* _d = KV + (buf) * 4 * 64 * ALDA; \
    _Pragma("unroll") \
    for (int _i = 0; _i < 16; _i++) { \
        int _idx = tid + _i * 128; \
        int _t = _idx >> 9, _r = (_idx >> 3) & 63, _s = _idx & 7; \
        cp_async16(smem_to_u32(_d + _t * 64 * ALDA + _r * ALDA + _s * 8), \
                   _srcs[_t] + base + (size_t)((kb) * 64 + _r) * EDIM + _s * 8); \
    } \
} while (0)

    ALOAD_KV(kb0, 0); CP_COMMIT();
    if (NB >= 2) { ALOAD_KV(kb0 + 1, 1); CP_COMMIT(); }

    const int b_nin = (lane & 7) + ((lane >= 16) ? 8 : 0);
    const int b_ch  = (lane >> 3) & 1;

    uint32_t qhf[4][4], qlf[4][4];
    float o[8][4];
#pragma unroll
    for (int nt = 0; nt < 8; nt++)
#pragma unroll
        for (int j = 0; j < 4; j++) o[nt][j] = 0.f;
    float m0 = -1e30f, m1 = -1e30f, l0 = 0.f, l1 = 0.f;
    const int i0 = q0 + wid * 16 + (lane >> 2);

    for (int j = 0; j < NB; j++) {
        if (j + 1 < NB) CP_WAIT1(); else CP_WAIT0();
        __syncthreads();
        if (j == 0) {
#pragma unroll
            for (int kt = 0; kt < 4; kt++) {
                uint32_t ah = smem_to_u32(&Qsh[(wid*16 + (lane & 15)) * ALDA + kt*16 + (lane >> 4)*8]);
                uint32_t al = smem_to_u32(&Qsl[(wid*16 + (lane & 15)) * ALDA + kt*16 + (lane >> 4)*8]);
                ldsm4(qhf[kt][0], qhf[kt][1], qhf[kt][2], qhf[kt][3], ah);
                ldsm4(qlf[kt][0], qlf[kt][1], qlf[kt][2], qlf[kt][3], al);
            }
        }
        const int kb = kb0 + j;
        const __nv_bfloat16* khs = KV + (j & 1) * 4 * 64 * ALDA;
        const __nv_bfloat16* kls = khs + 64 * ALDA;
        const __nv_bfloat16* vhs = khs + 2 * 64 * ALDA;
        const __nv_bfloat16* vls = khs + 3 * 64 * ALDA;

        float s[8][4];
#pragma unroll
        for (int nt = 0; nt < 8; nt++)
#pragma unroll
            for (int c = 0; c < 4; c++) s[nt][c] = 0.f;

#pragma unroll
        for (int kt = 0; kt < 4; kt++) {
            uint32_t bh[8][2], bl[8][2];
#pragma unroll
            for (int p = 0; p < 4; p++) {
                uint32_t r0, r1, r2, r3;
                uint32_t addr = smem_to_u32(&khs[(p*16 + b_nin) * ALDA + kt*16 + b_ch*8]);
                ldsm4(r0, r1, r2, r3, addr);
                bh[2*p][0] = r0; bh[2*p][1] = r1; bh[2*p+1][0] = r2; bh[2*p+1][1] = r3;
                addr = smem_to_u32(&kls[(p*16 + b_nin) * ALDA + kt*16 + b_ch*8]);
                ldsm4(r0, r1, r2, r3, addr);
                bl[2*p][0] = r0; bl[2*p][1] = r1; bl[2*p+1][0] = r2; bl[2*p+1][1] = r3;
            }
#pragma unroll
            for (int nt = 0; nt < 8; nt++) {
                mma16816(s[nt], qhf[kt][0], qhf[kt][1], qhf[kt][2], qhf[kt][3], bh[nt][0], bh[nt][1]);
                mma16816(s[nt], qhf[kt][0], qhf[kt][1], qhf[kt][2], qhf[kt][3], bl[nt][0], bl[nt][1]);
                mma16816(s[nt], qlf[kt][0], qlf[kt][1], qlf[kt][2], qlf[kt][3], bh[nt][0], bh[nt][1]);
            }
        }

        float mxA = -1e30f, mxB = -1e30f;
#pragma unroll
        for (int nt = 0; nt < 8; nt++) {
            int jb = kb * 64 + nt * 8 + (lane & 3) * 2;
            int d0 = i0 - jb;
            if ((unsigned)d0       > 256u) s[nt][0] = -1e30f;
            if ((unsigned)(d0 - 1) > 256u) s[nt][1] = -1e30f;
            if ((unsigned)(d0 + 8) > 256u) s[nt][2] = -1e30f;
            if ((unsigned)(d0 + 7) > 256u) s[nt][3] = -1e30f;
            mxA = fmaxf(mxA, fmaxf(s[nt][0], s[nt][1]));
            mxB = fmaxf(mxB, fmaxf(s[nt][2], s[nt][3]));
        }
        mxA = fmaxf(mxA, __shfl_xor_sync(0xffffffffu, mxA, 1));
        mxA = fmaxf(mxA, __shfl_xor_sync(0xffffffffu, mxA, 2));
        mxB = fmaxf(mxB, __shfl_xor_sync(0xffffffffu, mxB, 1));
        mxB = fmaxf(mxB, __shfl_xor_sync(0xffffffffu, mxB, 2));
        float nm0 = fmaxf(m0, mxA), nm1 = fmaxf(m1, mxB);
        float al0 = __expf(m0 - nm0), al1 = __expf(m1 - nm1);
        m0 = nm0; m1 = nm1;
        float rs0 = 0.f, rs1 = 0.f;
#pragma unroll
        for (int nt = 0; nt < 8; nt++) {
            s[nt][0] = __expf(s[nt][0] - m0);
            s[nt][1] = __expf(s[nt][1] - m0);
            s[nt][2] = __expf(s[nt][2] - m1);
            s[nt][3] = __expf(s[nt][3] - m1);
            rs0 += s[nt][0] + s[nt][1];
            rs1 += s[nt][2] + s[nt][3];
            o[nt][0] *= al0; o[nt][1] *= al0; o[nt][2] *= al1; o[nt][3] *= al1;
        }
        rs0 += __shfl_xor_sync(0xffffffffu, rs0, 1);
        rs0 += __shfl_xor_sync(0xffffffffu, rs0, 2);
        rs1 += __shfl_xor_sync(0xffffffffu, rs1, 1);
        rs1 += __shfl_xor_sync(0xffffffffu, rs1, 2);
        l0 = l0 * al0 + rs0;
        l1 = l1 * al1 + rs1;

#pragma unroll
        for (int kt = 0; kt < 4; kt++) {
            uint32_t pha[4], pla[4];
            {
                const int t0 = 2 * kt, t1 = 2 * kt + 1;
                __nv_bfloat16 h00 = __float2bfloat16_rn(s[t0][0]);
                __nv_bfloat16 h01 = __float2bfloat16_rn(s[t0][1]);
                __nv_bfloat16 h02 = __float2bfloat16_rn(s[t0][2]);
                __nv_bfloat16 h03 = __float2bfloat16_rn(s[t0][3]);
                __nv_bfloat16 h10 = __float2bfloat16_rn(s[t1][0]);
                __nv_bfloat16 h11 = __float2bfloat16_rn(s[t1][1]);
                __nv_bfloat16 h12 = __float2bfloat16_rn(s[t1][2]);
                __nv_bfloat16 h13 = __float2bfloat16_rn(s[t1][3]);
                pha[0] = ((uint32_t)*(uint16_t*)&h01 << 16) | *(uint16_t*)&h00;
                pha[1] = ((uint32_t)*(uint16_t*)&h03 << 16) | *(uint16_t*)&h02;
                pha[2] = ((uint32_t)*(uint16_t*)&h11 << 16) | *(uint16_t*)&h10;
                pha[3] = ((uint32_t)*(uint16_t*)&h13 << 16) | *(uint16_t*)&h12;
                pla[0] = packbf2(s[t0][0] - __bfloat162float(h00), s[t0][1] - __bfloat162float(h01));
                pla[1] = packbf2(s[t0][2] - __bfloat162float(h02), s[t0][3] - __bfloat162float(h03));
                pla[2] = packbf2(s[t1][0] - __bfloat162float(h10), s[t1][1] - __bfloat162float(h11));
                pla[3] = packbf2(s[t1][2] - __bfloat162float(h12), s[t1][3] - __bfloat162float(h13));
            }
#pragma unroll
            for (int p = 0; p < 4; p++) {
                uint32_t vrow = (kt*16 + ((lane >> 3) & 1)*8 + (lane & 7)) * ALDA + (p*2 + (lane >> 4))*8;
                uint32_t r0, r1, r2, r3, t0, t1, t2, t3;
                ldsm4t(r0, r1, r2, r3, smem_to_u32(&vhs[vrow]));
                ldsm4t(t0, t1, t2, t3, smem_to_u32(&vls[vrow]));
                mma16816(o[2*p],   pha[0], pha[1], pha[2], pha[3], r0, r1);
                mma16816(o[2*p],   pha[0], pha[1], pha[2], pha[3], t0, t1);
                mma16816(o[2*p],   pla[0], pla[1], pla[2], pla[3], r0, r1);
                mma16816(o[2*p+1], pha[0], pha[1], pha[2], pha[3], r2, r3);
                mma16816(o[2*p+1], pha[0], pha[1], pha[2], pha[3], t2, t3);
                mma16816(o[2*p+1], pla[0], pla[1], pla[2], pla[3], r2, r3);
            }
        }

        __syncthreads();
        if (j + 2 < NB) { ALOAD_KV(kb0 + j + 2, j & 1); CP_COMMIT(); }
    }
#undef ALOAD_KV

    const float inv0 = 1.0f / l0, inv1 = 1.0f / l1;
#pragma unroll
    for (int nt = 0; nt < 8; nt++) {
        const int col = nt * 8 + (lane & 3) * 2;
        float v0 = o[nt][0] * inv0, v1 = o[nt][1] * inv0;
        float v2 = o[nt][2] * inv1, v3 = o[nt][3] * inv1;
        __nv_bfloat16 h0 = __float2bfloat16_rn(v0), h1 = __float2bfloat16_rn(v1);
        __nv_bfloat16 h2 = __float2bfloat16_rn(v2), h3 = __float2bfloat16_rn(v3);
        size_t off0 = base + (size_t)i0 * EDIM + col;
        size_t off1 = base + (size_t)(i0 + 8) * EDIM + col;
        *(uint32_t*)(Oh + off0) = ((uint32_t)*(uint16_t*)&h1 << 16) | *(uint16_t*)&h0;
        *(uint32_t*)(Oh + off1) = ((uint32_t)*(uint16_t*)&h3 << 16) | *(uint16_t*)&h2;
        *(uint32_t*)(Ol + off0) = packbf2(v0 - __bfloat162float(h0), v1 - __bfloat162float(h1));
        *(uint32_t*)(Ol + off1) = packbf2(v2 - __bfloat162float(h2), v3 - __bfloat162float(h3));
    }
}

// ---------------- launch ----------------
extern "C" void kernel_launch(void* const* d_in, const int* in_sizes, int n_in,
                              void* d_out, int out_size)
{
    const float* x  = (const float*)d_in[0];
    const float* Wq = (const float*)d_in[1];
    const float* Wk = (const float*)d_in[2];
    const float* Wv = (const float*)d_in[3];
    const float* Wo = (const float*)d_in[4];
    const float* bq = (const float*)d_in[5];
    const float* bk = (const float*)d_in[6];
    const float* bv = (const float*)d_in[7];
    const float* bo = (const float*)d_in[8];

    __nv_bfloat16 *xh, *xl, *qh, *ql, *kh, *kl, *vh, *vl, *yh, *yl, *wh, *wl;
    cudaGetSymbolAddress((void**)&xh, g_xh);
    cudaGetSymbolAddress((void**)&xl, g_xl);
    cudaGetSymbolAddress((void**)&qh, g_qh);
    cudaGetSymbolAddress((void**)&ql, g_ql);
    cudaGetSymbolAddress((void**)&kh, g_kh);
    cudaGetSymbolAddress((void**)&kl, g_kl);
    cudaGetSymbolAddress((void**)&vh, g_vh);
    cudaGetSymbolAddress((void**)&vl, g_vl);
    cudaGetSymbolAddress((void**)&yh, g_yh);
    cudaGetSymbolAddress((void**)&yl, g_yl);
    cudaGetSymbolAddress((void**)&wh, g_wh);
    cudaGetSymbolAddress((void**)&wl, g_wl);

    static bool attr_done = false;
    if (!attr_done) {
        cudaFuncSetAttribute(gemm_tc3,  cudaFuncAttributeMaxDynamicSharedMemorySize, GEMM_SMEM);
        cudaFuncSetAttribute(swattn_tc, cudaFuncAttributeMaxDynamicSharedMemorySize, ATT_SMEM);
        attr_done = true;
    }

    const int NX4 = MROWS * EDIM / 4;   // 1,048,576
    const int NW4 = EDIM * EDIM / 4;    //   262,144
    const size_t WSZ = (size_t)EDIM * EDIM;

    // one fused split launch: x + 4 weights
    split5<<<dim3((NX4 + 255) / 256, 5), 256>>>(
        x, Wq, Wk, Wv, Wo,
        xh, xl, wh + 0*WSZ, wl + 0*WSZ, wh + 1*WSZ, wl + 1*WSZ,
        wh + 2*WSZ, wl + 2*WSZ, wh + 3*WSZ, wl + 3*WSZ, NX4, NW4);

    // fused QKV projection -> bf16 hi/lo outputs (q pre-scaled by 1/8)
    gemm_tc3<<<dim3(EDIM/BN, MROWS/BM, 3), 256, GEMM_SMEM>>>(
        xh, xl, wh, wl, bq, bk, bv, nullptr,
        qh, ql, kh, kl, vh, vl, 0.125f, 1);

    swattn_tc<<<dim3(SEQ/64, HEADS, BATCH), 128, ATT_SMEM>>>(
        qh, ql, kh, kl, vh, vl, yh, yl);

    // output projection -> fp32 d_out
    gemm_tc3<<<dim3(EDIM/BN, MROWS/BM, 1), 256, GEMM_SMEM>>>(
        yh, yl, wh + 3*WSZ, wl + 3*WSZ, bo, nullptr, nullptr,
        (float*)d_out, nullptr, nullptr, nullptr, nullptr, nullptr, nullptr, 1.0f, 0);
}

// round 7
// speedup vs baseline: 2.4487x; 1.0317x over previous
#include <cuda_runtime.h>
#include <cuda_bf16.h>
#include <cstdint>

#define EDIM  1024
#define HEADS 16
#define HD    64
#define WIN   256
#define BATCH 2
#define SEQ   2048
#define MROWS (BATCH*SEQ)   // 4096

// ---------------- scratch (allocation-free rule: device globals) ----------------
static __device__ __nv_bfloat16 g_xh[MROWS*EDIM];
static __device__ __nv_bfloat16 g_xl[MROWS*EDIM];
static __device__ __nv_bfloat16 g_qh[MROWS*EDIM];
static __device__ __nv_bfloat16 g_ql[MROWS*EDIM];
static __device__ __nv_bfloat16 g_kh[MROWS*EDIM];
static __device__ __nv_bfloat16 g_kl[MROWS*EDIM];
static __device__ __nv_bfloat16 g_vh[MROWS*EDIM];
static __device__ __nv_bfloat16 g_vl[MROWS*EDIM];
static __device__ __nv_bfloat16 g_yh[MROWS*EDIM];
static __device__ __nv_bfloat16 g_yl[MROWS*EDIM];
static __device__ __nv_bfloat16 g_wh[4][EDIM*EDIM];
static __device__ __nv_bfloat16 g_wl[4][EDIM*EDIM];

// ---------------- family-common PTX helpers ----------------
__device__ __forceinline__ uint32_t smem_to_u32(const void* p) {
    uint32_t a;
    asm("{ .reg .u64 t; cvta.to.shared.u64 t, %1; cvt.u32.u64 %0, t; }"
        : "=r"(a) : "l"(p));
    return a;
}
__device__ __forceinline__ void cp_async16(uint32_t dst, const void* src) {
    asm volatile("cp.async.cg.shared.global [%0], [%1], 16;" :: "r"(dst), "l"(src));
}
#define CP_COMMIT() asm volatile("cp.async.commit_group;" ::: "memory")
#define CP_WAIT1()  asm volatile("cp.async.wait_group 1;" ::: "memory")
#define CP_WAIT0()  asm volatile("cp.async.wait_group 0;" ::: "memory")

__device__ __forceinline__ void ldsm4(uint32_t& r0, uint32_t& r1, uint32_t& r2,
                                      uint32_t& r3, uint32_t addr) {
    asm volatile("ldmatrix.sync.aligned.m8n8.x4.shared.b16 {%0,%1,%2,%3}, [%4];"
                 : "=r"(r0), "=r"(r1), "=r"(r2), "=r"(r3) : "r"(addr));
}
__device__ __forceinline__ void ldsm4t(uint32_t& r0, uint32_t& r1, uint32_t& r2,
                                       uint32_t& r3, uint32_t addr) {
    asm volatile("ldmatrix.sync.aligned.m8n8.x4.trans.shared.b16 {%0,%1,%2,%3}, [%4];"
                 : "=r"(r0), "=r"(r1), "=r"(r2), "=r"(r3) : "r"(addr));
}
__device__ __forceinline__ void mma16816(float* c, uint32_t a0, uint32_t a1,
                                         uint32_t a2, uint32_t a3,
                                         uint32_t b0, uint32_t b1) {
    asm volatile(
        "mma.sync.aligned.m16n8k16.row.col.f32.bf16.bf16.f32 "
        "{%0,%1,%2,%3}, {%4,%5,%6,%7}, {%8,%9}, {%0,%1,%2,%3};"
        : "+f"(c[0]), "+f"(c[1]), "+f"(c[2]), "+f"(c[3])
        : "r"(a0), "r"(a1), "r"(a2), "r"(a3), "r"(b0), "r"(b1));
}
__device__ __forceinline__ uint32_t packbf2(float a, float b) {
    __nv_bfloat162 t = __floats2bfloat162_rn(a, b);
    return *(uint32_t*)&t;
}

// ---------------- fused fp32 -> bf16 hi/lo split (5 tensors, one launch) -------
__global__ __launch_bounds__(256)
void split5(const float* __restrict__ s0, const float* __restrict__ s1,
            const float* __restrict__ s2, const float* __restrict__ s3,
            const float* __restrict__ s4,
            __nv_bfloat16* __restrict__ h0, __nv_bfloat16* __restrict__ l0,
            __nv_bfloat16* __restrict__ h1, __nv_bfloat16* __restrict__ l1,
            __nv_bfloat16* __restrict__ h2, __nv_bfloat16* __restrict__ l2,
            __nv_bfloat16* __restrict__ h3, __nv_bfloat16* __restrict__ l3,
            __nv_bfloat16* __restrict__ h4, __nv_bfloat16* __restrict__ l4,
            int n0, int nw)
{
    const int t = blockIdx.y;
    const int n4 = (t == 0) ? n0 : nw;
    int i = blockIdx.x * 256 + threadIdx.x;
    if (i >= n4) return;
    const float* in = (t == 0) ? s0 : (t == 1) ? s1 : (t == 2) ? s2 : (t == 3) ? s3 : s4;
    __nv_bfloat16* hi = (t == 0) ? h0 : (t == 1) ? h1 : (t == 2) ? h2 : (t == 3) ? h3 : h4;
    __nv_bfloat16* lo = (t == 0) ? l0 : (t == 1) ? l1 : (t == 2) ? l2 : (t == 3) ? l3 : l4;
    float4 v = ((const float4*)in)[i];
    float vv[4] = {v.x, v.y, v.z, v.w};
    __nv_bfloat16 h[4], l[4];
#pragma unroll
    for (int j = 0; j < 4; j++) {
        h[j] = __float2bfloat16_rn(vv[j]);
        l[j] = __float2bfloat16_rn(vv[j] - __bfloat162float(h[j]));
    }
    ((uint2*)hi)[i] = *(uint2*)h;
    ((uint2*)lo)[i] = *(uint2*)l;
}

// ---------------- bf16 warp-MMA GEMM, 3-segment split-K ----------------
// 128x128 CTA tile, 4 warps each 64x64 (crossbar-balanced: 8 ldsm4 / 32 mma per ks)
#define BM   128
#define BN   128
#define BKC  64
#define LDSB 72
#define ATILE (BM*LDSB)
#define BTILE (BN*LDSB)
#define GEMM_SMEM (3*(ATILE+BTILE)*2)   // 110,592 B -> 2 CTAs/SM

__global__ __launch_bounds__(128, 2)
void gemm_tc3(const __nv_bfloat16* __restrict__ Ah, const __nv_bfloat16* __restrict__ Al,
              const __nv_bfloat16* __restrict__ Wh, const __nv_bfloat16* __restrict__ Wl,
              const float* __restrict__ b0v, const float* __restrict__ b1v,
              const float* __restrict__ b2v,
              float* __restrict__ Cf,
              __nv_bfloat16* __restrict__ H0, __nv_bfloat16* __restrict__ L0,
              __nv_bfloat16* __restrict__ H1, __nv_bfloat16* __restrict__ L1,
              __nv_bfloat16* __restrict__ H2, __nv_bfloat16* __restrict__ L2,
              float s0, int bf16out)
{
    extern __shared__ __align__(16) __nv_bfloat16 gsm[];
    __nv_bfloat16* As = gsm;
    __nv_bfloat16* Bs = gsm + 3 * ATILE;

    const int tid  = threadIdx.x;
    const int wid  = tid >> 5;
    const int lane = tid & 31;
    const int bm   = blockIdx.y * BM;
    const int bn   = blockIdx.x * BN;
    const int z    = blockIdx.z;
    const int wm   = (wid & 1) * 64;     // warp m offset (64-row slab)
    const int wn   = (wid >> 1) * 64;    // warp n offset (64-col slab)

    const __nv_bfloat16* Bh = Wh + (size_t)z * EDIM * EDIM + (size_t)bn * EDIM;
    const __nv_bfloat16* Bl = Wl + (size_t)z * EDIM * EDIM + (size_t)bn * EDIM;
    const __nv_bfloat16* Ahb = Ah + (size_t)bm * EDIM;
    const __nv_bfloat16* Alb = Al + (size_t)bm * EDIM;
    const float* bias = (z == 0) ? b0v : (z == 1) ? b1v : b2v;
    const float scale = (z == 0) ? s0 : 1.0f;

    const __nv_bfloat16* segA[3] = {Ahb, Ahb, Alb};
    const __nv_bfloat16* segB[3] = {Bh,  Bl,  Bh};

    float acc[4][8][4];
#pragma unroll
    for (int mt = 0; mt < 4; mt++)
#pragma unroll
        for (int nt = 0; nt < 8; nt++)
#pragma unroll
            for (int j = 0; j < 4; j++) acc[mt][nt][j] = 0.f;

    const int a_row = lane & 15, a_ch = lane >> 4;
    const int b_nin = (lane & 7) + ((lane >= 16) ? 8 : 0);
    const int b_ch  = (lane >> 3) & 1;

// 128 threads load A tile (128x64) + B tile (128x64): 8+8 segs of 16B each
#define LOADC(cc, st) do { \
    const int _seg = (cc) >> 4, _kc = (cc) & 15; \
    const __nv_bfloat16* _a = segA[_seg] + (size_t)_kc * BKC; \
    const __nv_bfloat16* _b = segB[_seg] + (size_t)_kc * BKC; \
    __nv_bfloat16* _as = As + (st) * ATILE; \
    __nv_bfloat16* _bs = Bs + (st) * BTILE; \
    _Pragma("unroll") \
    for (int _i = 0; _i < 8; _i++) { \
        int _idx = tid + _i * 128; int _r = _idx >> 3, _s = _idx & 7; \
        cp_async16(smem_to_u32(&_as[_r * LDSB + _s * 8]), _a + (size_t)_r * EDIM + _s * 8); \
        cp_async16(smem_to_u32(&_bs[_r * LDSB + _s * 8]), _b + (size_t)_r * EDIM + _s * 8); \
    } \
} while (0)

    const int NCH = 48;
    LOADC(0, 0); CP_COMMIT();
    LOADC(1, 1); CP_COMMIT();

    for (int c = 0; c < NCH; c++) {
        CP_WAIT1();
        __syncthreads();
        if (c + 2 < NCH) { LOADC(c + 2, (c + 2) % 3); CP_COMMIT(); }

        const __nv_bfloat16* as = As + (c % 3) * ATILE;
        const __nv_bfloat16* bs = Bs + (c % 3) * BTILE;
#pragma unroll
        for (int ks = 0; ks < 4; ks++) {
            const int k0 = ks * 16;
            uint32_t a[4][4];
#pragma unroll
            for (int mt = 0; mt < 4; mt++) {
                uint32_t addr = smem_to_u32(&as[(wm + mt * 16 + a_row) * LDSB + k0 + a_ch * 8]);
                ldsm4(a[mt][0], a[mt][1], a[mt][2], a[mt][3], addr);
            }
            uint32_t b[8][2];
#pragma unroll
            for (int p = 0; p < 4; p++) {
                uint32_t r0, r1, r2, r3;
                uint32_t addr = smem_to_u32(&bs[(wn + p * 16 + b_nin) * LDSB + k0 + b_ch * 8]);
                ldsm4(r0, r1, r2, r3, addr);
                b[2 * p][0] = r0;     b[2 * p][1] = r1;
                b[2 * p + 1][0] = r2; b[2 * p + 1][1] = r3;
            }
#pragma unroll
            for (int mt = 0; mt < 4; mt++)
#pragma unroll
                for (int nt = 0; nt < 8; nt++)
                    mma16816(acc[mt][nt], a[mt][0], a[mt][1], a[mt][2], a[mt][3],
                             b[nt][0], b[nt][1]);
        }
    }
#undef LOADC

    if (bf16out) {
        __nv_bfloat16* H = (z == 0) ? H0 : (z == 1) ? H1 : H2;
        __nv_bfloat16* L = (z == 0) ? L0 : (z == 1) ? L1 : L2;
#pragma unroll
        for (int nt = 0; nt < 8; nt++) {
            const int col = bn + wn + nt * 8 + (lane & 3) * 2;
            const float c0 = bias[col], c1 = bias[col + 1];
#pragma unroll
            for (int mt = 0; mt < 4; mt++) {
                const int r0 = bm + wm + mt * 16 + (lane >> 2);
#pragma unroll
                for (int rr = 0; rr < 2; rr++) {
                    float vx = (acc[mt][nt][2*rr+0] + c0) * scale;
                    float vy = (acc[mt][nt][2*rr+1] + c1) * scale;
                    __nv_bfloat16 hx = __float2bfloat16_rn(vx);
                    __nv_bfloat16 hy = __float2bfloat16_rn(vy);
                    float lx = vx - __bfloat162float(hx);
                    float ly = vy - __bfloat162float(hy);
                    size_t off = (size_t)(r0 + rr*8) * EDIM + col;
                    *(uint32_t*)(H + off) = ((uint32_t)*(uint16_t*)&hy << 16) | *(uint16_t*)&hx;
                    *(uint32_t*)(L + off) = packbf2(lx, ly);
                }
            }
        }
    } else {
#pragma unroll
        for (int nt = 0; nt < 8; nt++) {
            const int col = bn + wn + nt * 8 + (lane & 3) * 2;
            const float c0 = bias[col], c1 = bias[col + 1];
#pragma unroll
            for (int mt = 0; mt < 4; mt++) {
                const int r0 = bm + wm + mt * 16 + (lane >> 2);
                *(float2*)&Cf[(size_t)r0 * EDIM + col] =
                    make_float2((acc[mt][nt][0] + c0) * scale, (acc[mt][nt][1] + c1) * scale);
                *(float2*)&Cf[(size_t)(r0 + 8) * EDIM + col] =
                    make_float2((acc[mt][nt][2] + c0) * scale, (acc[mt][nt][3] + c1) * scale);
            }
        }
    }
}

// ---------------- sliding-window flash attention, bf16-split warp MMA ----------------
#define ALDA 72
#define ATT_SMEM ((2*64 + 2*4*64) * ALDA * 2)   // 92160 B

__global__ __launch_bounds__(128)
void swattn_tc(const __nv_bfloat16* __restrict__ Qh, const __nv_bfloat16* __restrict__ Ql,
               const __nv_bfloat16* __restrict__ Kh, const __nv_bfloat16* __restrict__ Kl,
               const __nv_bfloat16* __restrict__ Vh, const __nv_bfloat16* __restrict__ Vl,
               __nv_bfloat16* __restrict__ Oh, __nv_bfloat16* __restrict__ Ol)
{
    extern __shared__ __align__(16) __nv_bfloat16 sb[];
    __nv_bfloat16* Qsh = sb;
    __nv_bfloat16* Qsl = Qsh + 64 * ALDA;
    __nv_bfloat16* KV  = Qsl + 64 * ALDA;     // [buf][4][64*ALDA]

    const int tid = threadIdx.x, wid = tid >> 5, lane = tid & 31;
    const int qt = blockIdx.x, h = blockIdx.y, b = blockIdx.z;
    const int q0 = qt * 64;
    const size_t base = (size_t)b * SEQ * EDIM + (size_t)h * HD;
    const int kb0 = (qt > 4) ? qt - 4 : 0;
    const int NB  = qt - kb0 + 1;

    {
        const __nv_bfloat16* qs[2] = {Qh, Ql};
        __nv_bfloat16* qd[2] = {Qsh, Qsl};
#pragma unroll
        for (int i = 0; i < 8; i++) {
            int idx = tid + i * 128;
            int t = idx >> 9, r = (idx >> 3) & 63, s = idx & 7;
            cp_async16(smem_to_u32(qd[t] + r * ALDA + s * 8),
                       qs[t] + base + (size_t)(q0 + r) * EDIM + s * 8);
        }
    }
    CP_COMMIT();

#define ALOAD_KV(kb, buf) do { \
    const __nv_bfloat16* _srcs[4] = {Kh, Kl, Vh, Vl}; \
    __nv_bfloat16* _d = KV + (buf) * 4 * 64 * ALDA; \
    _Pragma("unroll") \
    for (int _i = 0; _i < 16; _i++) { \
        int _idx = tid + _i * 128; \
        int _t = _idx >> 9, _r = (_idx >> 3) & 63, _s = _idx & 7; \
        cp_async16(smem_to_u32(_d + _t * 64 * ALDA + _r * ALDA + _s * 8), \
                   _srcs[_t] + base + (size_t)((kb) * 64 + _r) * EDIM + _s * 8); \
    } \
} while (0)

    ALOAD_KV(kb0, 0); CP_COMMIT();
    if (NB >= 2) { ALOAD_KV(kb0 + 1, 1); CP_COMMIT(); }

    const int b_nin = (lane & 7) + ((lane >= 16) ? 8 : 0);
    const int b_ch  = (lane >> 3) & 1;

    uint32_t qhf[4][4], qlf[4][4];
    float o[8][4];
#pragma unroll
    for (int nt = 0; nt < 8; nt++)
#pragma unroll
        for (int j = 0; j < 4; j++) o[nt][j] = 0.f;
    float m0 = -1e30f, m1 = -1e30f, l0 = 0.f, l1 = 0.f;
    const int i0 = q0 + wid * 16 + (lane >> 2);

    for (int j = 0; j < NB; j++) {
        if (j + 1 < NB) CP_WAIT1(); else CP_WAIT0();
        __syncthreads();
        if (j == 0) {
#pragma unroll
            for (int kt = 0; kt < 4; kt++) {
                uint32_t ah = smem_to_u32(&Qsh[(wid*16 + (lane & 15)) * ALDA + kt*16 + (lane >> 4)*8]);
                uint32_t al = smem_to_u32(&Qsl[(wid*16 + (lane & 15)) * ALDA + kt*16 + (lane >> 4)*8]);
                ldsm4(qhf[kt][0], qhf[kt][1], qhf[kt][2], qhf[kt][3], ah);
                ldsm4(qlf[kt][0], qlf[kt][1], qlf[kt][2], qlf[kt][3], al);
            }
        }
        const int kb = kb0 + j;
        const __nv_bfloat16* khs = KV + (j & 1) * 4 * 64 * ALDA;
        const __nv_bfloat16* kls = khs + 64 * ALDA;
        const __nv_bfloat16* vhs = khs + 2 * 64 * ALDA;
        const __nv_bfloat16* vls = khs + 3 * 64 * ALDA;

        float s[8][4];
#pragma unroll
        for (int nt = 0; nt < 8; nt++)
#pragma unroll
            for (int c = 0; c < 4; c++) s[nt][c] = 0.f;

#pragma unroll
        for (int kt = 0; kt < 4; kt++) {
            uint32_t bh[8][2], bl[8][2];
#pragma unroll
            for (int p = 0; p < 4; p++) {
                uint32_t r0, r1, r2, r3;
                uint32_t addr = smem_to_u32(&khs[(p*16 + b_nin) * ALDA + kt*16 + b_ch*8]);
                ldsm4(r0, r1, r2, r3, addr);
                bh[2*p][0] = r0; bh[2*p][1] = r1; bh[2*p+1][0] = r2; bh[2*p+1][1] = r3;
                addr = smem_to_u32(&kls[(p*16 + b_nin) * ALDA + kt*16 + b_ch*8]);
                ldsm4(r0, r1, r2, r3, addr);
                bl[2*p][0] = r0; bl[2*p][1] = r1; bl[2*p+1][0] = r2; bl[2*p+1][1] = r3;
            }
#pragma unroll
            for (int nt = 0; nt < 8; nt++) {
                mma16816(s[nt], qhf[kt][0], qhf[kt][1], qhf[kt][2], qhf[kt][3], bh[nt][0], bh[nt][1]);
                mma16816(s[nt], qhf[kt][0], qhf[kt][1], qhf[kt][2], qhf[kt][3], bl[nt][0], bl[nt][1]);
                mma16816(s[nt], qlf[kt][0], qlf[kt][1], qlf[kt][2], qlf[kt][3], bh[nt][0], bh[nt][1]);
            }
        }

        float mxA = -1e30f, mxB = -1e30f;
#pragma unroll
        for (int nt = 0; nt < 8; nt++) {
            int jb = kb * 64 + nt * 8 + (lane & 3) * 2;
            int d0 = i0 - jb;
            if ((unsigned)d0       > 256u) s[nt][0] = -1e30f;
            if ((unsigned)(d0 - 1) > 256u) s[nt][1] = -1e30f;
            if ((unsigned)(d0 + 8) > 256u) s[nt][2] = -1e30f;
            if ((unsigned)(d0 + 7) > 256u) s[nt][3] = -1e30f;
            mxA = fmaxf(mxA, fmaxf(s[nt][0], s[nt][1]));
            mxB = fmaxf(mxB, fmaxf(s[nt][2], s[nt][3]));
        }
        mxA = fmaxf(mxA, __shfl_xor_sync(0xffffffffu, mxA, 1));
        mxA = fmaxf(mxA, __shfl_xor_sync(0xffffffffu, mxA, 2));
        mxB = fmaxf(mxB, __shfl_xor_sync(0xffffffffu, mxB, 1));
        mxB = fmaxf(mxB, __shfl_xor_sync(0xffffffffu, mxB, 2));
        float nm0 = fmaxf(m0, mxA), nm1 = fmaxf(m1, mxB);
        float al0 = __expf(m0 - nm0), al1 = __expf(m1 - nm1);
        m0 = nm0; m1 = nm1;
        float rs0 = 0.f, rs1 = 0.f;
#pragma unroll
        for (int nt = 0; nt < 8; nt++) {
            s[nt][0] = __expf(s[nt][0] - m0);
            s[nt][1] = __expf(s[nt][1] - m0);
            s[nt][2] = __expf(s[nt][2] - m1);
            s[nt][3] = __expf(s[nt][3] - m1);
            rs0 += s[nt][0] + s[nt][1];
            rs1 += s[nt][2] + s[nt][3];
            o[nt][0] *= al0; o[nt][1] *= al0; o[nt][2] *= al1; o[nt][3] *= al1;
        }
        rs0 += __shfl_xor_sync(0xffffffffu, rs0, 1);
        rs0 += __shfl_xor_sync(0xffffffffu, rs0, 2);
        rs1 += __shfl_xor_sync(0xffffffffu, rs1, 1);
        rs1 += __shfl_xor_sync(0xffffffffu, rs1, 2);
        l0 = l0 * al0 + rs0;
        l1 = l1 * al1 + rs1;

#pragma unroll
        for (int kt = 0; kt < 4; kt++) {
            uint32_t pha[4], pla[4];
            {
                const int t0 = 2 * kt, t1 = 2 * kt + 1;
                __nv_bfloat16 h00 = __float2bfloat16_rn(s[t0][0]);
                __nv_bfloat16 h01 = __float2bfloat16_rn(s[t0][1]);
                __nv_bfloat16 h02 = __float2bfloat16_rn(s[t0][2]);
                __nv_bfloat16 h03 = __float2bfloat16_rn(s[t0][3]);
                __nv_bfloat16 h10 = __float2bfloat16_rn(s[t1][0]);
                __nv_bfloat16 h11 = __float2bfloat16_rn(s[t1][1]);
                __nv_bfloat16 h12 = __float2bfloat16_rn(s[t1][2]);
                __nv_bfloat16 h13 = __float2bfloat16_rn(s[t1][3]);
                pha[0] = ((uint32_t)*(uint16_t*)&h01 << 16) | *(uint16_t*)&h00;
                pha[1] = ((uint32_t)*(uint16_t*)&h03 << 16) | *(uint16_t*)&h02;
                pha[2] = ((uint32_t)*(uint16_t*)&h11 << 16) | *(uint16_t*)&h10;
                pha[3] = ((uint32_t)*(uint16_t*)&h13 << 16) | *(uint16_t*)&h12;
                pla[0] = packbf2(s[t0][0] - __bfloat162float(h00), s[t0][1] - __bfloat162float(h01));
                pla[1] = packbf2(s[t0][2] - __bfloat162float(h02), s[t0][3] - __bfloat162float(h03));
                pla[2] = packbf2(s[t1][0] - __bfloat162float(h10), s[t1][1] - __bfloat162float(h11));
                pla[3] = packbf2(s[t1][2] - __bfloat162float(h12), s[t1][3] - __bfloat162float(h13));
            }
#pragma unroll
            for (int p = 0; p < 4; p++) {
                uint32_t vrow = (kt*16 + ((lane >> 3) & 1)*8 + (lane & 7)) * ALDA + (p*2 + (lane >> 4))*8;
                uint32_t r0, r1, r2, r3, t0, t1, t2, t3;
                ldsm4t(r0, r1, r2, r3, smem_to_u32(&vhs[vrow]));
                ldsm4t(t0, t1, t2, t3, smem_to_u32(&vls[vrow]));
                mma16816(o[2*p],   pha[0], pha[1], pha[2], pha[3], r0, r1);
                mma16816(o[2*p],   pha[0], pha[1], pha[2], pha[3], t0, t1);
                mma16816(o[2*p],   pla[0], pla[1], pla[2], pla[3], r0, r1);
                mma16816(o[2*p+1], pha[0], pha[1], pha[2], pha[3], r2, r3);
                mma16816(o[2*p+1], pha[0], pha[1], pha[2], pha[3], t2, t3);
                mma16816(o[2*p+1], pla[0], pla[1], pla[2], pla[3], r2, r3);
            }
        }

        __syncthreads();
        if (j + 2 < NB) { ALOAD_KV(kb0 + j + 2, j & 1); CP_COMMIT(); }
    }
#undef ALOAD_KV

    const float inv0 = 1.0f / l0, inv1 = 1.0f / l1;
#pragma unroll
    for (int nt = 0; nt < 8; nt++) {
        const int col = nt * 8 + (lane & 3) * 2;
        float v0 = o[nt][0] * inv0, v1 = o[nt][1] * inv0;
        float v2 = o[nt][2] * inv1, v3 = o[nt][3] * inv1;
        __nv_bfloat16 h0 = __float2bfloat16_rn(v0), h1 = __float2bfloat16_rn(v1);
        __nv_bfloat16 h2 = __float2bfloat16_rn(v2), h3 = __float2bfloat16_rn(v3);
        size_t off0 = base + (size_t)i0 * EDIM + col;
        size_t off1 = base + (size_t)(i0 + 8) * EDIM + col;
        *(uint32_t*)(Oh + off0) = ((uint32_t)*(uint16_t*)&h1 << 16) | *(uint16_t*)&h0;
        *(uint32_t*)(Oh + off1) = ((uint32_t)*(uint16_t*)&h3 << 16) | *(uint16_t*)&h2;
        *(uint32_t*)(Ol + off0) = packbf2(v0 - __bfloat162float(h0), v1 - __bfloat162float(h1));
        *(uint32_t*)(Ol + off1) = packbf2(v2 - __bfloat162float(h2), v3 - __bfloat162float(h3));
    }
}

// ---------------- launch ----------------
extern "C" void kernel_launch(void* const* d_in, const int* in_sizes, int n_in,
                              void* d_out, int out_size)
{
    const float* x  = (const float*)d_in[0];
    const float* Wq = (const float*)d_in[1];
    const float* Wk = (const float*)d_in[2];
    const float* Wv = (const float*)d_in[3];
    const float* Wo = (const float*)d_in[4];
    const float* bq = (const float*)d_in[5];
    const float* bk = (const float*)d_in[6];
    const float* bv = (const float*)d_in[7];
    const float* bo = (const float*)d_in[8];

    __nv_bfloat16 *xh, *xl, *qh, *ql, *kh, *kl, *vh, *vl, *yh, *yl, *wh, *wl;
    cudaGetSymbolAddress((void**)&xh, g_xh);
    cudaGetSymbolAddress((void**)&xl, g_xl);
    cudaGetSymbolAddress((void**)&qh, g_qh);
    cudaGetSymbolAddress((void**)&ql, g_ql);
    cudaGetSymbolAddress((void**)&kh, g_kh);
    cudaGetSymbolAddress((void**)&kl, g_kl);
    cudaGetSymbolAddress((void**)&vh, g_vh);
    cudaGetSymbolAddress((void**)&vl, g_vl);
    cudaGetSymbolAddress((void**)&yh, g_yh);
    cudaGetSymbolAddress((void**)&yl, g_yl);
    cudaGetSymbolAddress((void**)&wh, g_wh);
    cudaGetSymbolAddress((void**)&wl, g_wl);

    static bool attr_done = false;
    if (!attr_done) {
        cudaFuncSetAttribute(gemm_tc3,  cudaFuncAttributeMaxDynamicSharedMemorySize, GEMM_SMEM);
        cudaFuncSetAttribute(swattn_tc, cudaFuncAttributeMaxDynamicSharedMemorySize, ATT_SMEM);
        attr_done = true;
    }

    const int NX4 = MROWS * EDIM / 4;   // 1,048,576
    const int NW4 = EDIM * EDIM / 4;    //   262,144
    const size_t WSZ = (size_t)EDIM * EDIM;

    split5<<<dim3((NX4 + 255) / 256, 5), 256>>>(
        x, Wq, Wk, Wv, Wo,
        xh, xl, wh + 0*WSZ, wl + 0*WSZ, wh + 1*WSZ, wl + 1*WSZ,
        wh + 2*WSZ, wl + 2*WSZ, wh + 3*WSZ, wl + 3*WSZ, NX4, NW4);

    // fused QKV projection -> bf16 hi/lo outputs (q pre-scaled by 1/8)
    gemm_tc3<<<dim3(EDIM/BN, MROWS/BM, 3), 128, GEMM_SMEM>>>(
        xh, xl, wh, wl, bq, bk, bv, nullptr,
        qh, ql, kh, kl, vh, vl, 0.125f, 1);

    swattn_tc<<<dim3(SEQ/64, HEADS, BATCH), 128, ATT_SMEM>>>(
        qh, ql, kh, kl, vh, vl, yh, yl);

    // output projection -> fp32 d_out
    gemm_tc3<<<dim3(EDIM/BN, MROWS/BM, 1), 128, GEMM_SMEM>>>(
        yh, yl, wh + 3*WSZ, wl + 3*WSZ, bo, nullptr, nullptr,
        (float*)d_out, nullptr, nullptr, nullptr, nullptr, nullptr, nullptr, 1.0f, 0);
}